// round 10
// baseline (speedup 1.0000x reference)
#include <cuda_runtime.h>

#define NN 100000
#define EE 1600000
#define TOTE 1700000
#define D 128
#define ZA 0.8f
#define ZB 0.2f
#define NEG 0.2f
#define NBLK 98     // ceil(NN / 1024)
#define NAGG 12500  // NN / 8  (exact)

// ---------------- scratch (device globals; no runtime allocation) ----------------
__device__ __align__(256) float  g_xp[NN * D];
__device__ __align__(256) float  g_acc[NN * D];
__device__ __align__(256) float  g_asrc[NN];
__device__ __align__(256) float  g_adst[NN];
__device__ __align__(256) int    g_src[TOTE];
__device__ __align__(256) int    g_dst[TOTE];
__device__ __align__(256) int    g_deg[NN];
__device__ __align__(256) int    g_rowptr[NN + 1];
__device__ __align__(256) int    g_pos[NN];
__device__ __align__(256) int    g_esrc[TOTE];
__device__ __align__(256) float  g_eex[TOTE];
__device__ __align__(256) int    g_bsum[NBLK];
__device__ __align__(256) int    g_boff[NBLK];
__device__ __align__(256) unsigned char g_mask[NN];
__device__ __align__(256) float  g_psum[NAGG * D];  // per-agg-block column sums
__device__ __align__(256) float  g_psq [NAGG * D];  // per-agg-block column sumsq
__device__ __align__(256) double g_cs[D];
__device__ __align__(256) double g_cq[D];
__device__ __align__(256) float  g_A[D];
__device__ __align__(256) float  g_B[D];
// pre-split (tf32 hi/lo) weights
__device__ __align__(256) float  g_W0h[D * D], g_W0l[D * D];
__device__ __align__(256) float  g_W1h[D * D], g_W1l[D * D];
__device__ __align__(256) float  g_GWh[D * D], g_GWl[D * D];
__device__ __align__(256) float  g_Wah[D * 2 * D], g_Wal[D * 2 * D];
__device__ __align__(256) float  g_Wbh[D * 2 * D], g_Wbl[D * 2 * D];
__device__ __align__(256) float  g_ba[D];
__device__ __align__(256) float  g_bb[D];
__device__ __align__(256) int    g_listT[NN];
__device__ __align__(256) int    g_listF[NN];
__device__            int        g_cnt[2];
__device__            int        g_flags[2];

// ---------------- tf32x3 helpers ----------------
__device__ __forceinline__ float tff(float f) {
    unsigned u; asm("cvt.rna.tf32.f32 %0, %1;" : "=r"(u) : "f"(f));
    return __uint_as_float(u);
}
__device__ __forceinline__ void sp3(float f, float& h, float& l) {
    h = tff(f);
    l = tff(f - h);
}
__device__ __forceinline__ void mma8(float4& d, const unsigned a[4], unsigned b0, unsigned b1) {
    asm volatile("mma.sync.aligned.m16n8k8.row.col.f32.tf32.tf32.f32 "
                 "{%0,%1,%2,%3},{%4,%5,%6,%7},{%8,%9},{%0,%1,%2,%3};"
                 : "+f"(d.x), "+f"(d.y), "+f"(d.z), "+f"(d.w)
                 : "r"(a[0]), "r"(a[1]), "r"(a[2]), "r"(a[3]), "r"(b0), "r"(b1));
}
// D += A*B with tf32x3 compensation (drops lo*lo term)
__device__ __forceinline__ void mma3(float4& d, const unsigned ah[4], const unsigned al[4],
                                     unsigned bh0, unsigned bh1, unsigned bl0, unsigned bl1) {
    mma8(d, al, bh0, bh1);
    mma8(d, ah, bl0, bl1);
    mma8(d, ah, bh0, bh1);
}

// ---------------- detect dtypes + zero counters ----------------
__global__ __launch_bounds__(256) void k_detect(const void* ei, const void* mask) {
    int i = blockIdx.x * 256 + threadIdx.x;
    if (i < NN) g_deg[i] = 0;
    if (i < D) { g_cs[i] = 0.0; g_cq[i] = 0.0; }
    if (i == 0) {
        g_cnt[0] = 0; g_cnt[1] = 0;
        const int* e32 = (const int*)ei;
        int allz = 1;
        for (int k = 1; k < 128; k += 2) if (e32[k] != 0) { allz = 0; break; }
        g_flags[0] = allz;
        const unsigned int* m32 = (const unsigned int*)mask;
        int int_like = 1, float_like = 1;
        for (int k = 0; k < 256; k++) {
            unsigned int w = m32[k];
            if (!(w == 0u || w == 1u)) int_like = 0;
            if (!(w == 0u || w == 0x3F800000u)) float_like = 0;
        }
        g_flags[1] = int_like ? 1 : (float_like ? 2 : 0);
    }
}

// ---------------- split static weights to tf32 hi/lo ----------------
__global__ __launch_bounds__(256) void k_splitw(const float* __restrict__ W0,
                                                const float* __restrict__ W1,
                                                const float* __restrict__ GW) {
    int i = blockIdx.x * 256 + threadIdx.x;
    if (i < D * D) {
        float h, l;
        sp3(W0[i], h, l); g_W0h[i] = h; g_W0l[i] = l;
        sp3(W1[i], h, l); g_W1h[i] = h; g_W1l[i] = l;
        sp3(GW[i], h, l); g_GWh[i] = h; g_GWl[i] = l;
    }
}

// ---------------- normalize inputs + degree histogram + mask compaction ----------------
__global__ __launch_bounds__(256) void k_convert(const void* ei, const void* maskp) {
    int i = blockIdx.x * 256 + threadIdx.x;
    int e64 = g_flags[0], mk = g_flags[1];
    if (i < TOTE) {
        int s, d;
        if (i < EE) {
            if (e64) {
                const long long* e = (const long long*)ei;
                s = (int)e[i]; d = (int)e[EE + i];
            } else {
                const int* e = (const int*)ei;
                s = e[i]; d = e[EE + i];
            }
        } else { s = d = i - EE; }
        g_src[i] = s; g_dst[i] = d;
        if ((unsigned)s < NN && (unsigned)d < NN) atomicAdd(&g_deg[d], 1);
    }
    if (i < NN) {
        unsigned char m;
        if (mk == 0)      m = ((const unsigned char*)maskp)[i] != 0;
        else if (mk == 1) m = ((const int*)maskp)[i] != 0;
        else              m = ((const float*)maskp)[i] != 0.f;
        g_mask[i] = m;
        if (m) g_listT[atomicAdd(&g_cnt[0], 1)] = i;
        else   g_listF[atomicAdd(&g_cnt[1], 1)] = i;
    }
}

// ---------------- two-level exclusive scan over degrees ----------------
__global__ __launch_bounds__(1024) void k_scan1() {
    __shared__ int sh[1024];
    int b = blockIdx.x, t = threadIdx.x;
    int i = b * 1024 + t;
    sh[t] = (i < NN) ? g_deg[i] : 0;
    __syncthreads();
    for (int off = 512; off > 0; off >>= 1) {
        if (t < off) sh[t] += sh[t + off];
        __syncthreads();
    }
    if (t == 0) g_bsum[b] = sh[0];
}
__global__ void k_scan2() {
    if (threadIdx.x != 0) return;
    int run = 0;
    for (int b = 0; b < NBLK; b++) { g_boff[b] = run; run += g_bsum[b]; }
    g_rowptr[NN] = run;
}
__global__ __launch_bounds__(1024) void k_scan3() {
    __shared__ int sh[1024];
    int b = blockIdx.x, t = threadIdx.x;
    int i = b * 1024 + t;
    int v = (i < NN) ? g_deg[i] : 0;
    sh[t] = v;
    __syncthreads();
    int acc = v;
    for (int off = 1; off < 1024; off <<= 1) {
        int add = (t >= off) ? sh[t - off] : 0;
        __syncthreads();
        acc += add;
        sh[t] = acc;
        __syncthreads();
    }
    if (i < NN) {
        int ex = acc - v + g_boff[b];
        g_rowptr[i] = ex;
        g_pos[i] = ex;
    }
}

// ---------------- fused transform+GAT, tf32x3, hoisted splits ----------------
// Aliased smem layout (42.6 KB total):
//  [0,640)        : sPS(256) sPD(256) sM(64) + pad
//  [640,34432)    : sX 64x132 fp32       (live: stage1-epilogue .. end)
//    stage1 aliases inside sX span (dead once sX written):
//    [640,3712)   sAh   [3712,6784)  sAl
//    [6784,10880) sB0h  [10880,14976) sB0l
//    [14976,19072) sB1h [19072,23168) sB1l
//  [34432,38528)  sGh   [38528,42624) sGl   (stage2 B tiles)
__global__ __launch_bounds__(256) void k_tg(
    const float* __restrict__ x,
    const float* __restrict__ b0v, const float* __restrict__ b1v,
    const float* __restrict__ att_s, const float* __restrict__ att_d)
{
    __shared__ __align__(16) char smem_[42624];
    float* sPS = (float*)smem_;
    float* sPD = sPS + 64;
    unsigned char* sM = (unsigned char*)(sPD + 64);
    float* sX   = (float*)(smem_ + 640);
    float* sAh  = (float*)(smem_ + 640);
    float* sAl  = (float*)(smem_ + 3712);
    float* sB0h = (float*)(smem_ + 6784);
    float* sB0l = (float*)(smem_ + 10880);
    float* sB1h = (float*)(smem_ + 14976);
    float* sB1l = (float*)(smem_ + 19072);
    float* sGh  = (float*)(smem_ + 34432);
    float* sGl  = (float*)(smem_ + 38528);

    int tid = threadIdx.x, lane = tid & 31, warp = tid >> 5;
    int wm = warp >> 2, wn = warp & 3;
    int g = lane >> 2, t = lane & 3;
    int base = blockIdx.x * 64;

    if (tid < 64) {
        sPS[tid] = 0.f; sPD[tid] = 0.f;
        int gr = base + tid;
        sM[tid] = (gr < NN) ? g_mask[gr] : (unsigned char)0;
    }

    float4 acc0[2][4], acc1[2][4];
#pragma unroll
    for (int mt = 0; mt < 2; mt++)
#pragma unroll
        for (int nt = 0; nt < 4; nt++) {
            acc0[mt][nt] = make_float4(0.f, 0.f, 0.f, 0.f);
            acc1[mt][nt] = make_float4(0.f, 0.f, 0.f, 0.f);
        }

    // ---- stage 1: dual tf32x3 GEMM, pre-split operands in smem ----
    for (int kc = 0; kc < 16; kc++) {
        if (tid < 128) {
            int row = tid >> 1, seg = tid & 1, grow = base + row;
            float4 av = make_float4(0.f, 0.f, 0.f, 0.f);
            if (grow < NN) av = *(const float4*)&x[(size_t)grow * D + kc * 8 + seg * 4];
            float4 hv, lv;
            sp3(av.x, hv.x, lv.x); sp3(av.y, hv.y, lv.y);
            sp3(av.z, hv.z, lv.z); sp3(av.w, hv.w, lv.w);
            *(float4*)&sAh[row * 12 + seg * 4] = hv;
            *(float4*)&sAl[row * 12 + seg * 4] = lv;
        }
        {
            int j = tid >> 1, seg = tid & 1;
            int go = j * D + kc * 8 + seg * 4, so = j * 8 + seg * 4;
            *(float4*)&sB0h[so] = *(const float4*)&g_W0h[go];
            *(float4*)&sB0l[so] = *(const float4*)&g_W0l[go];
            *(float4*)&sB1h[so] = *(const float4*)&g_W1h[go];
            *(float4*)&sB1l[so] = *(const float4*)&g_W1l[go];
        }
        __syncthreads();
        unsigned ah[2][4], al[2][4];
#pragma unroll
        for (int mt = 0; mt < 2; mt++) {
            int r = wm * 32 + mt * 16 + g;
            ah[mt][0] = __float_as_uint(sAh[r * 12 + t]);
            ah[mt][1] = __float_as_uint(sAh[(r + 8) * 12 + t]);
            ah[mt][2] = __float_as_uint(sAh[r * 12 + t + 4]);
            ah[mt][3] = __float_as_uint(sAh[(r + 8) * 12 + t + 4]);
            al[mt][0] = __float_as_uint(sAl[r * 12 + t]);
            al[mt][1] = __float_as_uint(sAl[(r + 8) * 12 + t]);
            al[mt][2] = __float_as_uint(sAl[r * 12 + t + 4]);
            al[mt][3] = __float_as_uint(sAl[(r + 8) * 12 + t + 4]);
        }
#pragma unroll
        for (int nt = 0; nt < 4; nt++) {
            int n = wn * 32 + nt * 8 + g;
            unsigned bh0 = __float_as_uint(sB0h[n * 8 + t]);
            unsigned bh1 = __float_as_uint(sB0h[n * 8 + t + 4]);
            unsigned bl0 = __float_as_uint(sB0l[n * 8 + t]);
            unsigned bl1 = __float_as_uint(sB0l[n * 8 + t + 4]);
            mma3(acc0[0][nt], ah[0], al[0], bh0, bh1, bl0, bl1);
            mma3(acc0[1][nt], ah[1], al[1], bh0, bh1, bl0, bl1);
            bh0 = __float_as_uint(sB1h[n * 8 + t]);
            bh1 = __float_as_uint(sB1h[n * 8 + t + 4]);
            bl0 = __float_as_uint(sB1l[n * 8 + t]);
            bl1 = __float_as_uint(sB1l[n * 8 + t + 4]);
            mma3(acc1[0][nt], ah[0], al[0], bh0, bh1, bl0, bl1);
            mma3(acc1[1][nt], ah[1], al[1], bh0, bh1, bl0, bl1);
        }
        __syncthreads();
    }

    // ---- stage-1 epilogue: bias + relu + mix -> sX (overwrites dead A/B tiles) ----
#pragma unroll
    for (int nt = 0; nt < 4; nt++) {
        int cn = wn * 32 + nt * 8 + t * 2;
        float b0x = b0v[cn], b0y = b0v[cn + 1];
        float b1x = b1v[cn], b1y = b1v[cn + 1];
#pragma unroll
        for (int mt = 0; mt < 2; mt++) {
            int r0 = wm * 32 + mt * 16 + g;
            bool m0 = sM[r0] != 0, m1 = sM[r0 + 8] != 0;
            float4 u0 = acc0[mt][nt], u1 = acc1[mt][nt];
            float v0, v1, ra, rb;
            v0 = fmaxf(u0.x + b0x, 0.f); v1 = fmaxf(u1.x + b1x, 0.f);
            ra = m0 ? (ZA * v1 + ZB * v0) : (ZA * v0 + ZB * v1);
            v0 = fmaxf(u0.y + b0y, 0.f); v1 = fmaxf(u1.y + b1y, 0.f);
            rb = m0 ? (ZA * v1 + ZB * v0) : (ZA * v0 + ZB * v1);
            *(float2*)&sX[r0 * 132 + cn] = make_float2(ra, rb);
            v0 = fmaxf(u0.z + b0x, 0.f); v1 = fmaxf(u1.z + b1x, 0.f);
            ra = m1 ? (ZA * v1 + ZB * v0) : (ZA * v0 + ZB * v1);
            v0 = fmaxf(u0.w + b0y, 0.f); v1 = fmaxf(u1.w + b1y, 0.f);
            rb = m1 ? (ZA * v1 + ZB * v0) : (ZA * v0 + ZB * v1);
            *(float2*)&sX[(r0 + 8) * 132 + cn] = make_float2(ra, rb);
        }
    }
    __syncthreads();

    // ---- stage 2: xp = sX @ GW^T (A split per-lane, B pre-split) ----
#pragma unroll
    for (int mt = 0; mt < 2; mt++)
#pragma unroll
        for (int nt = 0; nt < 4; nt++)
            acc0[mt][nt] = make_float4(0.f, 0.f, 0.f, 0.f);

    for (int kc = 0; kc < 16; kc++) {
        {
            int j = tid >> 1, seg = tid & 1;
            int go = j * D + kc * 8 + seg * 4, so = j * 8 + seg * 4;
            *(float4*)&sGh[so] = *(const float4*)&g_GWh[go];
            *(float4*)&sGl[so] = *(const float4*)&g_GWl[go];
        }
        __syncthreads();
        unsigned ah[2][4], al[2][4];
#pragma unroll
        for (int mt = 0; mt < 2; mt++) {
            int r = wm * 32 + mt * 16 + g;
            float h, l;
            sp3(sX[r * 132 + kc * 8 + t], h, l);
            ah[mt][0] = __float_as_uint(h); al[mt][0] = __float_as_uint(l);
            sp3(sX[(r + 8) * 132 + kc * 8 + t], h, l);
            ah[mt][1] = __float_as_uint(h); al[mt][1] = __float_as_uint(l);
            sp3(sX[r * 132 + kc * 8 + t + 4], h, l);
            ah[mt][2] = __float_as_uint(h); al[mt][2] = __float_as_uint(l);
            sp3(sX[(r + 8) * 132 + kc * 8 + t + 4], h, l);
            ah[mt][3] = __float_as_uint(h); al[mt][3] = __float_as_uint(l);
        }
#pragma unroll
        for (int nt = 0; nt < 4; nt++) {
            int n = wn * 32 + nt * 8 + g;
            unsigned bh0 = __float_as_uint(sGh[n * 8 + t]);
            unsigned bh1 = __float_as_uint(sGh[n * 8 + t + 4]);
            unsigned bl0 = __float_as_uint(sGl[n * 8 + t]);
            unsigned bl1 = __float_as_uint(sGl[n * 8 + t + 4]);
            mma3(acc0[0][nt], ah[0], al[0], bh0, bh1, bl0, bl1);
            mma3(acc0[1][nt], ah[1], al[1], bh0, bh1, bl0, bl1);
        }
        __syncthreads();
    }

    // ---- stage-2 epilogue: write xp, reduce attention dots ----
    float asx[4][2], adx[4][2];
#pragma unroll
    for (int nt = 0; nt < 4; nt++) {
        int cn = wn * 32 + nt * 8 + t * 2;
        asx[nt][0] = att_s[cn]; asx[nt][1] = att_s[cn + 1];
        adx[nt][0] = att_d[cn]; adx[nt][1] = att_d[cn + 1];
    }
#pragma unroll
    for (int mt = 0; mt < 2; mt++) {
        float p0 = 0.f, p1 = 0.f, q0 = 0.f, q1 = 0.f;
#pragma unroll
        for (int nt = 0; nt < 4; nt++) {
            float4 u = acc0[mt][nt];
            p0 += u.x * asx[nt][0] + u.y * asx[nt][1];
            q0 += u.x * adx[nt][0] + u.y * adx[nt][1];
            p1 += u.z * asx[nt][0] + u.w * asx[nt][1];
            q1 += u.z * adx[nt][0] + u.w * adx[nt][1];
        }
        p0 += __shfl_xor_sync(0xFFFFFFFFu, p0, 1); p0 += __shfl_xor_sync(0xFFFFFFFFu, p0, 2);
        q0 += __shfl_xor_sync(0xFFFFFFFFu, q0, 1); q0 += __shfl_xor_sync(0xFFFFFFFFu, q0, 2);
        p1 += __shfl_xor_sync(0xFFFFFFFFu, p1, 1); p1 += __shfl_xor_sync(0xFFFFFFFFu, p1, 2);
        q1 += __shfl_xor_sync(0xFFFFFFFFu, q1, 1); q1 += __shfl_xor_sync(0xFFFFFFFFu, q1, 2);
        if (t == 0) {
            int r0 = wm * 32 + mt * 16 + g;
            atomicAdd(&sPS[r0], p0);     atomicAdd(&sPD[r0], q0);
            atomicAdd(&sPS[r0 + 8], p1); atomicAdd(&sPD[r0 + 8], q1);
        }
    }
#pragma unroll
    for (int mt = 0; mt < 2; mt++)
#pragma unroll
        for (int nt = 0; nt < 4; nt++) {
            int r0 = base + wm * 32 + mt * 16 + g;
            int cn = wn * 32 + nt * 8 + t * 2;
            float4 u = acc0[mt][nt];
            if (r0 < NN)     *(float2*)&g_xp[(size_t)r0 * D + cn]       = make_float2(u.x, u.y);
            if (r0 + 8 < NN) *(float2*)&g_xp[(size_t)(r0 + 8) * D + cn] = make_float2(u.z, u.w);
        }
    __syncthreads();
    if (tid < 64) {
        int gr = base + tid;
        if (gr < NN) { g_asrc[gr] = sPS[tid]; g_adst[gr] = sPD[tid]; }
    }
}

// ---------------- fill dst-sorted edge lists + per-edge exp weights ----------------
__global__ __launch_bounds__(256) void k_fill() {
    int e = blockIdx.x * 256 + threadIdx.x;
    if (e >= TOTE) return;
    int s = g_src[e], d = g_dst[e];
    if ((unsigned)s >= NN || (unsigned)d >= NN) return;
    float al = g_asrc[s] + g_adst[d];
    al = al > 0.f ? al : NEG * al;
    float ex = expf(al);
    int p = atomicAdd(&g_pos[d], 1);
    g_esrc[p] = s;
    g_eex[p] = ex;
}

// ---------------- gather-aggregate + fused GraphNorm partial stats ----------------
// one warp per dst node; block = 8 nodes (12500 blocks x 8 = 100000 exactly)
__global__ __launch_bounds__(256) void k_agg() {
    __shared__ float sSum[128], sSq[128];
    int tid = threadIdx.x, lane = tid & 31;
    int wg = blockIdx.x * 8 + (tid >> 5);
    if (tid < 128) { sSum[tid] = 0.f; sSq[tid] = 0.f; }
    __syncthreads();

    if (wg < NN) {
        int beg = g_rowptr[wg], end = g_rowptr[wg + 1];
        float4 a0 = make_float4(0.f, 0.f, 0.f, 0.f);
        float4 a1 = make_float4(0.f, 0.f, 0.f, 0.f);
        float d0 = 0.f, d1 = 0.f;
        for (int b = beg; b < end; b += 32) {
            int myi = b + lane;
            int sl = 0; float exl = 0.f;
            if (myi < end) { sl = __ldg(&g_esrc[myi]); exl = __ldg(&g_eex[myi]); }
            int m = min(32, end - b);
            int j = 0;
            for (; j + 2 <= m; j += 2) {
                int   s0 = __shfl_sync(0xFFFFFFFFu, sl, j);
                float e0 = __shfl_sync(0xFFFFFFFFu, exl, j);
                int   s1 = __shfl_sync(0xFFFFFFFFu, sl, j + 1);
                float e1 = __shfl_sync(0xFFFFFFFFu, exl, j + 1);
                float4 v0 = __ldg((const float4*)&g_xp[(size_t)s0 * D + lane * 4]);
                float4 v1 = __ldg((const float4*)&g_xp[(size_t)s1 * D + lane * 4]);
                a0.x = fmaf(v0.x, e0, a0.x); a0.y = fmaf(v0.y, e0, a0.y);
                a0.z = fmaf(v0.z, e0, a0.z); a0.w = fmaf(v0.w, e0, a0.w);
                a1.x = fmaf(v1.x, e1, a1.x); a1.y = fmaf(v1.y, e1, a1.y);
                a1.z = fmaf(v1.z, e1, a1.z); a1.w = fmaf(v1.w, e1, a1.w);
                d0 += e0; d1 += e1;
            }
            if (j < m) {
                int   s0 = __shfl_sync(0xFFFFFFFFu, sl, j);
                float e0 = __shfl_sync(0xFFFFFFFFu, exl, j);
                float4 v0 = __ldg((const float4*)&g_xp[(size_t)s0 * D + lane * 4]);
                a0.x = fmaf(v0.x, e0, a0.x); a0.y = fmaf(v0.y, e0, a0.y);
                a0.z = fmaf(v0.z, e0, a0.z); a0.w = fmaf(v0.w, e0, a0.w);
                d0 += e0;
            }
        }
        float inv = 1.f / (d0 + d1 + 1e-16f);
        float4 o = make_float4((a0.x + a1.x) * inv, (a0.y + a1.y) * inv,
                               (a0.z + a1.z) * inv, (a0.w + a1.w) * inv);
        *(float4*)&g_acc[(size_t)wg * D + lane * 4] = o;
        int c = lane * 4;
        atomicAdd(&sSum[c + 0], o.x); atomicAdd(&sSq[c + 0], o.x * o.x);
        atomicAdd(&sSum[c + 1], o.y); atomicAdd(&sSq[c + 1], o.y * o.y);
        atomicAdd(&sSum[c + 2], o.z); atomicAdd(&sSq[c + 2], o.z * o.z);
        atomicAdd(&sSum[c + 3], o.w); atomicAdd(&sSq[c + 3], o.w * o.w);
    }
    __syncthreads();
    if (tid < 128) {
        g_psum[blockIdx.x * 128 + tid] = sSum[tid];
        g_psq [blockIdx.x * 128 + tid] = sSq[tid];
    }
}

// ---------------- reduce partials to double sums ----------------
__global__ __launch_bounds__(128) void k_red1() {
    int c = threadIdx.x;
    double s = 0.0, q = 0.0;
    for (int b = blockIdx.x; b < NAGG; b += gridDim.x) {
        s += (double)g_psum[b * 128 + c];
        q += (double)g_psq [b * 128 + c];
    }
    atomicAdd(&g_cs[c], s);
    atomicAdd(&g_cq[c], q);
}

// ---------------- GraphNorm coefficients (stats exclude bias; adjust here) ----------------
__global__ void k_red2(const float* __restrict__ gnw, const float* __restrict__ gnb,
                       const float* __restrict__ gms, const float* __restrict__ gatb) {
    int c = threadIdx.x;
    double S = g_cs[c], Q = g_cq[c];
    double b = (double)gatb[c];
    double m  = (S + (double)NN * b) / (double)NN;           // E[acc + bias]
    double e2 = (Q + 2.0 * b * S + (double)NN * b * b) / (double)NN;
    double s  = (double)gms[c];
    double var = e2 - 2.0 * s * m * m + s * s * m * m;
    double A = (double)gnw[c] / sqrt(var + 1e-5);
    double B = (double)gnb[c] - s * m * A;
    g_A[c] = (float)A;
    g_B[c] = (float)(b * A + B);
}

// ---------------- precompute mixed + norm-scaled final weights, pre-split ----------------
__global__ __launch_bounds__(256) void k_prep(const float* __restrict__ Wc0, const float* __restrict__ bc0,
                                              const float* __restrict__ Wc1, const float* __restrict__ bc1) {
    __shared__ float2 rr[256];
    int j = blockIdx.x, c = threadIdx.x;
    float w0 = Wc0[j * 256 + c], w1 = Wc1[j * 256 + c];
    float wa = ZA * w1 + ZB * w0;
    float wb = ZA * w0 + ZB * w1;
    float pa = 0.f, pb = 0.f;
    if (c < D) {
        float Bv = g_B[c], A = g_A[c];
        pa = wa * Bv; pb = wb * Bv;
        wa *= A; wb *= A;
    }
    float h, l;
    sp3(wa, h, l); g_Wah[j * 256 + c] = h; g_Wal[j * 256 + c] = l;
    sp3(wb, h, l); g_Wbh[j * 256 + c] = h; g_Wbl[j * 256 + c] = l;
    rr[c] = make_float2(pa, pb);
    __syncthreads();
    for (int off = 128; off > 0; off >>= 1) {
        if (c < off) { rr[c].x += rr[c + off].x; rr[c].y += rr[c + off].y; }
        __syncthreads();
    }
    if (c == 0) {
        g_ba[j] = ZA * bc1[j] + ZB * bc0[j] + rr[0].x;
        g_bb[j] = ZA * bc0[j] + ZB * bc1[j] + rr[0].y;
    }
}

// ---------------- final GEMM (tf32x3, pre-split operands) ----------------
template <int WHICH>
__global__ __launch_bounds__(256) void k_final(const float* __restrict__ x_, float* __restrict__ out) {
    __shared__ __align__(16) float sAh[64 * 12], sAl[64 * 12];
    __shared__ __align__(16) float sBh[128 * 8], sBl[128 * 8];
    __shared__ int sIdx[64];
    int cnt = g_cnt[WHICH];
    int base = blockIdx.x * 64;
    if (base >= cnt) return;
    const int*   list = (WHICH == 0) ? g_listT : g_listF;
    const float* Wh   = (WHICH == 0) ? g_Wah : g_Wbh;
    const float* Wl   = (WHICH == 0) ? g_Wal : g_Wbl;
    const float* bias = (WHICH == 0) ? g_ba : g_bb;
    int tid = threadIdx.x, lane = tid & 31, warp = tid >> 5;
    int wm = warp >> 2, wn = warp & 3;
    int g = lane >> 2, t = lane & 3;
    if (tid < 64) sIdx[tid] = (base + tid < cnt) ? list[base + tid] : -1;
    __syncthreads();

    float4 acc[2][4];
#pragma unroll
    for (int mt = 0; mt < 2; mt++)
#pragma unroll
        for (int nt = 0; nt < 4; nt++) acc[mt][nt] = make_float4(0.f, 0.f, 0.f, 0.f);

    for (int kc = 0; kc < 32; kc++) {
        if (tid < 128) {
            int row = tid >> 1, seg = tid & 1;
            int aidx = sIdx[row];
            int k0 = kc * 8 + seg * 4;
            float4 av = make_float4(0.f, 0.f, 0.f, 0.f);
            if (aidx >= 0) {
                if (k0 < D) av = *(const float4*)&g_acc[(size_t)aidx * D + k0];
                else        av = *(const float4*)&x_[(size_t)aidx * D + (k0 - D)];
            }
            float4 hv, lv;
            sp3(av.x, hv.x, lv.x); sp3(av.y, hv.y, lv.y);
            sp3(av.z, hv.z, lv.z); sp3(av.w, hv.w, lv.w);
            *(float4*)&sAh[row * 12 + seg * 4] = hv;
            *(float4*)&sAl[row * 12 + seg * 4] = lv;
        }
        {
            int j = tid >> 1, seg = tid & 1;
            int go = j * 256 + kc * 8 + seg * 4, so = j * 8 + seg * 4;
            *(float4*)&sBh[so] = *(const float4*)&Wh[go];
            *(float4*)&sBl[so] = *(const float4*)&Wl[go];
        }
        __syncthreads();
        unsigned ah[2][4], al[2][4];
#pragma unroll
        for (int mt = 0; mt < 2; mt++) {
            int r = wm * 32 + mt * 16 + g;
            ah[mt][0] = __float_as_uint(sAh[r * 12 + t]);
            ah[mt][1] = __float_as_uint(sAh[(r + 8) * 12 + t]);
            ah[mt][2] = __float_as_uint(sAh[r * 12 + t + 4]);
            ah[mt][3] = __float_as_uint(sAh[(r + 8) * 12 + t + 4]);
            al[mt][0] = __float_as_uint(sAl[r * 12 + t]);
            al[mt][1] = __float_as_uint(sAl[(r + 8) * 12 + t]);
            al[mt][2] = __float_as_uint(sAl[r * 12 + t + 4]);
            al[mt][3] = __float_as_uint(sAl[(r + 8) * 12 + t + 4]);
        }
#pragma unroll
        for (int nt = 0; nt < 4; nt++) {
            int n = wn * 32 + nt * 8 + g;
            unsigned bh0 = __float_as_uint(sBh[n * 8 + t]);
            unsigned bh1 = __float_as_uint(sBh[n * 8 + t + 4]);
            unsigned bl0 = __float_as_uint(sBl[n * 8 + t]);
            unsigned bl1 = __float_as_uint(sBl[n * 8 + t + 4]);
            mma3(acc[0][nt], ah[0], al[0], bh0, bh1, bl0, bl1);
            mma3(acc[1][nt], ah[1], al[1], bh0, bh1, bl0, bl1);
        }
        __syncthreads();
    }
#pragma unroll
    for (int nt = 0; nt < 4; nt++) {
        int cn = wn * 32 + nt * 8 + t * 2;
        float bx = bias[cn], by = bias[cn + 1];
#pragma unroll
        for (int mt = 0; mt < 2; mt++) {
            int r = wm * 32 + mt * 16 + g;
            int i0 = sIdx[r], i1 = sIdx[r + 8];
            float4 u = acc[mt][nt];
            if (i0 >= 0) *(float2*)&out[(size_t)i0 * D + cn] = make_float2(u.x + bx, u.y + by);
            if (i1 >= 0) *(float2*)&out[(size_t)i1 * D + cn] = make_float2(u.z + bx, u.w + by);
        }
    }
}

// ---------------- launch ----------------
extern "C" void kernel_launch(void* const* d_in, const int* in_sizes, int n_in,
                              void* d_out, int out_size) {
    const float* x_      = (const float*)d_in[0];
    const float* W_t0    = (const float*)d_in[2];
    const float* b_t0    = (const float*)d_in[3];
    const float* W_t1    = (const float*)d_in[4];
    const float* b_t1    = (const float*)d_in[5];
    const float* gat_W   = (const float*)d_in[6];
    const float* att_src = (const float*)d_in[7];
    const float* att_dst = (const float*)d_in[8];
    const float* gat_b   = (const float*)d_in[9];
    const float* gn_w    = (const float*)d_in[10];
    const float* gn_b    = (const float*)d_in[11];
    const float* gn_ms   = (const float*)d_in[12];
    const float* W_c0    = (const float*)d_in[13];
    const float* b_c0    = (const float*)d_in[14];
    const float* W_c1    = (const float*)d_in[15];
    const float* b_c1    = (const float*)d_in[16];
    const void*  ei      = d_in[17];
    const void*  mask    = d_in[18];
    float* out = (float*)d_out;

    int gb = (NN + 63) / 64;

    k_detect<<<(NN + 255) / 256, 256>>>(ei, mask);
    k_splitw<<<(D * D + 255) / 256, 256>>>(W_t0, W_t1, gat_W);
    k_convert<<<(TOTE + 255) / 256, 256>>>(ei, mask);
    k_scan1<<<NBLK, 1024>>>();
    k_scan2<<<1, 32>>>();
    k_scan3<<<NBLK, 1024>>>();
    k_tg<<<gb, 256>>>(x_, b_t0, b_t1, att_src, att_dst);
    k_fill<<<(TOTE + 255) / 256, 256>>>();
    k_agg<<<NAGG, 256>>>();
    k_red1<<<64, 128>>>();
    k_red2<<<1, 128>>>(gn_w, gn_b, gn_ms, gat_b);
    k_prep<<<128, 256>>>(W_c0, b_c0, W_c1, b_c1);
    k_final<0><<<gb, 256>>>(x_, out);
    k_final<1><<<gb, 256>>>(x_, out);
}

// round 11
// speedup vs baseline: 1.1677x; 1.1677x over previous
#include <cuda_runtime.h>

#define NN 100000
#define EE 1600000
#define TOTE 1700000
#define D 128
#define ZA 0.8f
#define ZB 0.2f
#define NEG 0.2f
#define NBLK 98   // ceil(NN / 1024)

// ---------------- scratch (device globals; no runtime allocation) ----------------
__device__ __align__(256) float  g_xp[NN * D];
__device__ __align__(256) float  g_acc[NN * D];
__device__ __align__(256) float  g_asrc[NN];
__device__ __align__(256) float  g_adst[NN];
__device__ __align__(256) int    g_src[TOTE];
__device__ __align__(256) int    g_dst[TOTE];
__device__ __align__(256) int    g_deg[NN];
__device__ __align__(256) int    g_rowptr[NN + 1];
__device__ __align__(256) int    g_pos[NN];
__device__ __align__(256) int    g_esrc[TOTE];
__device__ __align__(256) float  g_eex[TOTE];
__device__ __align__(256) int    g_bsum[NBLK];
__device__ __align__(256) int    g_boff[NBLK];
__device__ __align__(256) unsigned char g_mask[NN];
__device__ __align__(256) double g_cs[D];
__device__ __align__(256) double g_cq[D];
__device__ __align__(256) float  g_A[D];
__device__ __align__(256) float  g_B[D];
__device__ __align__(256) float  g_Wa[D * 2 * D];
__device__ __align__(256) float  g_Wb[D * 2 * D];
__device__ __align__(256) float  g_ba[D];
__device__ __align__(256) float  g_bb[D];
__device__ __align__(256) int    g_listT[NN];
__device__ __align__(256) int    g_listF[NN];
__device__            int        g_cnt[2];
__device__            int        g_flags[2];

// ---------------- tf32x3 helpers ----------------
__device__ __forceinline__ float tff(float f) {
    unsigned u; asm("cvt.rna.tf32.f32 %0, %1;" : "=r"(u) : "f"(f));
    return __uint_as_float(u);
}
__device__ __forceinline__ void sp3(float f, unsigned& h, unsigned& l) {
    float hf = tff(f);
    h = __float_as_uint(hf);
    l = __float_as_uint(tff(f - hf));
}
__device__ __forceinline__ void mma8(float4& d, const unsigned a[4], unsigned b0, unsigned b1) {
    asm volatile("mma.sync.aligned.m16n8k8.row.col.f32.tf32.tf32.f32 "
                 "{%0,%1,%2,%3},{%4,%5,%6,%7},{%8,%9},{%0,%1,%2,%3};"
                 : "+f"(d.x), "+f"(d.y), "+f"(d.z), "+f"(d.w)
                 : "r"(a[0]), "r"(a[1]), "r"(a[2]), "r"(a[3]), "r"(b0), "r"(b1));
}
// D += A*B with tf32x3 compensation (drops lo*lo term, ~2e-7 rel)
__device__ __forceinline__ void mma3(float4& d, const unsigned ah[4], const unsigned al[4],
                                     unsigned bh0, unsigned bh1, unsigned bl0, unsigned bl1) {
    mma8(d, al, bh0, bh1);
    mma8(d, ah, bl0, bl1);
    mma8(d, ah, bh0, bh1);
}

// ---------------- detect dtypes + zero counters (launch 1) ----------------
__global__ __launch_bounds__(256) void k_detect(const void* ei, const void* mask) {
    int i = blockIdx.x * 256 + threadIdx.x;
    if (i < NN) g_deg[i] = 0;
    if (i < D) { g_cs[i] = 0.0; g_cq[i] = 0.0; }
    if (i == 0) {
        g_cnt[0] = 0; g_cnt[1] = 0;
        const int* e32 = (const int*)ei;
        int allz = 1;
        for (int k = 1; k < 128; k += 2) if (e32[k] != 0) { allz = 0; break; }
        g_flags[0] = allz;
        const unsigned int* m32 = (const unsigned int*)mask;
        int int_like = 1, float_like = 1;
        for (int k = 0; k < 256; k++) {
            unsigned int w = m32[k];
            if (!(w == 0u || w == 1u)) int_like = 0;
            if (!(w == 0u || w == 0x3F800000u)) float_like = 0;
        }
        g_flags[1] = int_like ? 1 : (float_like ? 2 : 0);
    }
}

// ---------------- normalize inputs + degree histogram + mask compaction (launch 2) ----------------
__global__ __launch_bounds__(256) void k_convert(const void* ei, const void* maskp) {
    int i = blockIdx.x * 256 + threadIdx.x;
    int e64 = g_flags[0], mk = g_flags[1];
    if (i < TOTE) {
        int s, d;
        if (i < EE) {
            if (e64) {
                const long long* e = (const long long*)ei;
                s = (int)e[i]; d = (int)e[EE + i];
            } else {
                const int* e = (const int*)ei;
                s = e[i]; d = e[EE + i];
            }
        } else { s = d = i - EE; }
        g_src[i] = s; g_dst[i] = d;
        if ((unsigned)s < NN && (unsigned)d < NN) atomicAdd(&g_deg[d], 1);
    }
    if (i < NN) {
        unsigned char m;
        if (mk == 0)      m = ((const unsigned char*)maskp)[i] != 0;
        else if (mk == 1) m = ((const int*)maskp)[i] != 0;
        else              m = ((const float*)maskp)[i] != 0.f;
        g_mask[i] = m;
        if (m) g_listT[atomicAdd(&g_cnt[0], 1)] = i;
        else   g_listF[atomicAdd(&g_cnt[1], 1)] = i;
    }
}

// ---------------- scan level 1 (launch 3) ----------------
__global__ __launch_bounds__(1024) void k_scan1() {
    __shared__ int sh[1024];
    int b = blockIdx.x, t = threadIdx.x;
    int i = b * 1024 + t;
    sh[t] = (i < NN) ? g_deg[i] : 0;
    __syncthreads();
    for (int off = 512; off > 0; off >>= 1) {
        if (t < off) sh[t] += sh[t + off];
        __syncthreads();
    }
    if (t == 0) g_bsum[b] = sh[0];
}

// ---------------- fused transform+GAT, tf32x3 inline splits (launch 4 -> PROFILED) ----------------
__global__ __launch_bounds__(256) void k_tg(
    const float* __restrict__ x,
    const float* __restrict__ W0, const float* __restrict__ b0v,
    const float* __restrict__ W1, const float* __restrict__ b1v,
    const float* __restrict__ GW,
    const float* __restrict__ att_s, const float* __restrict__ att_d)
{
    __shared__ __align__(16) float sX[64 * 132];
    __shared__ __align__(16) float sA[64 * 12];
    __shared__ __align__(16) float sB0[128 * 8];
    __shared__ __align__(16) float sB1[128 * 8];
    __shared__ float sPS[64], sPD[64];
    __shared__ unsigned char sM[64];

    int tid = threadIdx.x, lane = tid & 31, warp = tid >> 5;
    int wm = warp >> 2, wn = warp & 3;
    int g = lane >> 2, t = lane & 3;
    int base = blockIdx.x * 64;

    if (tid < 64) {
        sPS[tid] = 0.f; sPD[tid] = 0.f;
        int gr = base + tid;
        sM[tid] = (gr < NN) ? g_mask[gr] : (unsigned char)0;
    }

    float4 acc0[2][4], acc1[2][4];
#pragma unroll
    for (int mt = 0; mt < 2; mt++)
#pragma unroll
        for (int nt = 0; nt < 4; nt++) {
            acc0[mt][nt] = make_float4(0.f, 0.f, 0.f, 0.f);
            acc1[mt][nt] = make_float4(0.f, 0.f, 0.f, 0.f);
        }

    // ---- stage 1: dual tf32x3 GEMM over K=128 ----
    for (int kc = 0; kc < 16; kc++) {
        if (tid < 128) {
            int row = tid >> 1, seg = tid & 1, grow = base + row;
            float4 av = make_float4(0.f, 0.f, 0.f, 0.f);
            if (grow < NN) av = *(const float4*)&x[(size_t)grow * D + kc * 8 + seg * 4];
            *(float4*)&sA[row * 12 + seg * 4] = av;
        }
        {
            int j = tid >> 1, seg = tid & 1;
            *(float4*)&sB0[j * 8 + seg * 4] = *(const float4*)&W0[j * D + kc * 8 + seg * 4];
            *(float4*)&sB1[j * 8 + seg * 4] = *(const float4*)&W1[j * D + kc * 8 + seg * 4];
        }
        __syncthreads();
        unsigned ah[2][4], al[2][4];
#pragma unroll
        for (int mt = 0; mt < 2; mt++) {
            int r = wm * 32 + mt * 16 + g;
            sp3(sA[r * 12 + t],           ah[mt][0], al[mt][0]);
            sp3(sA[(r + 8) * 12 + t],     ah[mt][1], al[mt][1]);
            sp3(sA[r * 12 + t + 4],       ah[mt][2], al[mt][2]);
            sp3(sA[(r + 8) * 12 + t + 4], ah[mt][3], al[mt][3]);
        }
#pragma unroll
        for (int nt = 0; nt < 4; nt++) {
            int n = wn * 32 + nt * 8 + g;
            unsigned bh0, bl0, bh1, bl1;
            sp3(sB0[n * 8 + t],     bh0, bl0);
            sp3(sB0[n * 8 + t + 4], bh1, bl1);
            mma3(acc0[0][nt], ah[0], al[0], bh0, bh1, bl0, bl1);
            mma3(acc0[1][nt], ah[1], al[1], bh0, bh1, bl0, bl1);
            sp3(sB1[n * 8 + t],     bh0, bl0);
            sp3(sB1[n * 8 + t + 4], bh1, bl1);
            mma3(acc1[0][nt], ah[0], al[0], bh0, bh1, bl0, bl1);
            mma3(acc1[1][nt], ah[1], al[1], bh0, bh1, bl0, bl1);
        }
        __syncthreads();
    }

    // ---- stage-1 epilogue: bias + relu + mix -> sX ----
#pragma unroll
    for (int nt = 0; nt < 4; nt++) {
        int cn = wn * 32 + nt * 8 + t * 2;
        float b0x = b0v[cn], b0y = b0v[cn + 1];
        float b1x = b1v[cn], b1y = b1v[cn + 1];
#pragma unroll
        for (int mt = 0; mt < 2; mt++) {
            int r0 = wm * 32 + mt * 16 + g;
            bool m0 = sM[r0] != 0, m1 = sM[r0 + 8] != 0;
            float4 u0 = acc0[mt][nt], u1 = acc1[mt][nt];
            float v0, v1, ra, rb;
            v0 = fmaxf(u0.x + b0x, 0.f); v1 = fmaxf(u1.x + b1x, 0.f);
            ra = m0 ? (ZA * v1 + ZB * v0) : (ZA * v0 + ZB * v1);
            v0 = fmaxf(u0.y + b0y, 0.f); v1 = fmaxf(u1.y + b1y, 0.f);
            rb = m0 ? (ZA * v1 + ZB * v0) : (ZA * v0 + ZB * v1);
            *(float2*)&sX[r0 * 132 + cn] = make_float2(ra, rb);
            v0 = fmaxf(u0.z + b0x, 0.f); v1 = fmaxf(u1.z + b1x, 0.f);
            ra = m1 ? (ZA * v1 + ZB * v0) : (ZA * v0 + ZB * v1);
            v0 = fmaxf(u0.w + b0y, 0.f); v1 = fmaxf(u1.w + b1y, 0.f);
            rb = m1 ? (ZA * v1 + ZB * v0) : (ZA * v0 + ZB * v1);
            *(float2*)&sX[(r0 + 8) * 132 + cn] = make_float2(ra, rb);
        }
    }
    __syncthreads();

    // ---- stage 2: xp = sX @ GW^T (tf32x3) ----
#pragma unroll
    for (int mt = 0; mt < 2; mt++)
#pragma unroll
        for (int nt = 0; nt < 4; nt++)
            acc0[mt][nt] = make_float4(0.f, 0.f, 0.f, 0.f);

    for (int kc = 0; kc < 16; kc++) {
        {
            int j = tid >> 1, seg = tid & 1;
            *(float4*)&sB0[j * 8 + seg * 4] = *(const float4*)&GW[j * D + kc * 8 + seg * 4];
        }
        __syncthreads();
        unsigned ah[2][4], al[2][4];
#pragma unroll
        for (int mt = 0; mt < 2; mt++) {
            int r = wm * 32 + mt * 16 + g;
            sp3(sX[r * 132 + kc * 8 + t],           ah[mt][0], al[mt][0]);
            sp3(sX[(r + 8) * 132 + kc * 8 + t],     ah[mt][1], al[mt][1]);
            sp3(sX[r * 132 + kc * 8 + t + 4],       ah[mt][2], al[mt][2]);
            sp3(sX[(r + 8) * 132 + kc * 8 + t + 4], ah[mt][3], al[mt][3]);
        }
#pragma unroll
        for (int nt = 0; nt < 4; nt++) {
            int n = wn * 32 + nt * 8 + g;
            unsigned bh0, bl0, bh1, bl1;
            sp3(sB0[n * 8 + t],     bh0, bl0);
            sp3(sB0[n * 8 + t + 4], bh1, bl1);
            mma3(acc0[0][nt], ah[0], al[0], bh0, bh1, bl0, bl1);
            mma3(acc0[1][nt], ah[1], al[1], bh0, bh1, bl0, bl1);
        }
        __syncthreads();
    }

    // ---- stage-2 epilogue: write xp, reduce attention dots ----
    float asx[4][2], adx[4][2];
#pragma unroll
    for (int nt = 0; nt < 4; nt++) {
        int cn = wn * 32 + nt * 8 + t * 2;
        asx[nt][0] = att_s[cn]; asx[nt][1] = att_s[cn + 1];
        adx[nt][0] = att_d[cn]; adx[nt][1] = att_d[cn + 1];
    }
#pragma unroll
    for (int mt = 0; mt < 2; mt++) {
        float p0 = 0.f, p1 = 0.f, q0 = 0.f, q1 = 0.f;
#pragma unroll
        for (int nt = 0; nt < 4; nt++) {
            float4 u = acc0[mt][nt];
            p0 += u.x * asx[nt][0] + u.y * asx[nt][1];
            q0 += u.x * adx[nt][0] + u.y * adx[nt][1];
            p1 += u.z * asx[nt][0] + u.w * asx[nt][1];
            q1 += u.z * adx[nt][0] + u.w * adx[nt][1];
        }
        p0 += __shfl_xor_sync(0xFFFFFFFFu, p0, 1); p0 += __shfl_xor_sync(0xFFFFFFFFu, p0, 2);
        q0 += __shfl_xor_sync(0xFFFFFFFFu, q0, 1); q0 += __shfl_xor_sync(0xFFFFFFFFu, q0, 2);
        p1 += __shfl_xor_sync(0xFFFFFFFFu, p1, 1); p1 += __shfl_xor_sync(0xFFFFFFFFu, p1, 2);
        q1 += __shfl_xor_sync(0xFFFFFFFFu, q1, 1); q1 += __shfl_xor_sync(0xFFFFFFFFu, q1, 2);
        if (t == 0) {
            int r0 = wm * 32 + mt * 16 + g;
            atomicAdd(&sPS[r0], p0);     atomicAdd(&sPD[r0], q0);
            atomicAdd(&sPS[r0 + 8], p1); atomicAdd(&sPD[r0 + 8], q1);
        }
    }
#pragma unroll
    for (int mt = 0; mt < 2; mt++)
#pragma unroll
        for (int nt = 0; nt < 4; nt++) {
            int r0 = base + wm * 32 + mt * 16 + g;
            int cn = wn * 32 + nt * 8 + t * 2;
            float4 u = acc0[mt][nt];
            if (r0 < NN)     *(float2*)&g_xp[(size_t)r0 * D + cn]       = make_float2(u.x, u.y);
            if (r0 + 8 < NN) *(float2*)&g_xp[(size_t)(r0 + 8) * D + cn] = make_float2(u.z, u.w);
        }
    __syncthreads();
    if (tid < 64) {
        int gr = base + tid;
        if (gr < NN) { g_asrc[gr] = sPS[tid]; g_adst[gr] = sPD[tid]; }
    }
}

// ---------------- scan levels 2/3 ----------------
__global__ void k_scan2() {
    if (threadIdx.x != 0) return;
    int run = 0;
    for (int b = 0; b < NBLK; b++) { g_boff[b] = run; run += g_bsum[b]; }
    g_rowptr[NN] = run;
}
__global__ __launch_bounds__(1024) void k_scan3() {
    __shared__ int sh[1024];
    int b = blockIdx.x, t = threadIdx.x;
    int i = b * 1024 + t;
    int v = (i < NN) ? g_deg[i] : 0;
    sh[t] = v;
    __syncthreads();
    int acc = v;
    for (int off = 1; off < 1024; off <<= 1) {
        int add = (t >= off) ? sh[t - off] : 0;
        __syncthreads();
        acc += add;
        sh[t] = acc;
        __syncthreads();
    }
    if (i < NN) {
        int ex = acc - v + g_boff[b];
        g_rowptr[i] = ex;
        g_pos[i] = ex;
    }
}

// ---------------- fill dst-sorted edge lists + per-edge exp weights ----------------
__global__ __launch_bounds__(256) void k_fill() {
    int e = blockIdx.x * 256 + threadIdx.x;
    if (e >= TOTE) return;
    int s = g_src[e], d = g_dst[e];
    if ((unsigned)s >= NN || (unsigned)d >= NN) return;
    float al = g_asrc[s] + g_adst[d];
    al = al > 0.f ? al : NEG * al;
    float ex = expf(al);
    int p = atomicAdd(&g_pos[d], 1);
    g_esrc[p] = s;
    g_eex[p] = ex;
}

// ---------------- gather-aggregate: one warp per dst, 2x unrolled ----------------
__global__ __launch_bounds__(256) void k_agg() {
    int wg = (blockIdx.x * 256 + threadIdx.x) >> 5;
    int lane = threadIdx.x & 31;
    if (wg >= NN) return;
    int beg = g_rowptr[wg], end = g_rowptr[wg + 1];
    float4 a0 = make_float4(0.f, 0.f, 0.f, 0.f);
    float4 a1 = make_float4(0.f, 0.f, 0.f, 0.f);
    float d0 = 0.f, d1 = 0.f;
    for (int b = beg; b < end; b += 32) {
        int myi = b + lane;
        int sl = 0; float exl = 0.f;
        if (myi < end) { sl = __ldg(&g_esrc[myi]); exl = __ldg(&g_eex[myi]); }
        int m = min(32, end - b);
        int j = 0;
        for (; j + 2 <= m; j += 2) {
            int   s0 = __shfl_sync(0xFFFFFFFFu, sl, j);
            float e0 = __shfl_sync(0xFFFFFFFFu, exl, j);
            int   s1 = __shfl_sync(0xFFFFFFFFu, sl, j + 1);
            float e1 = __shfl_sync(0xFFFFFFFFu, exl, j + 1);
            float4 v0 = __ldg((const float4*)&g_xp[(size_t)s0 * D + lane * 4]);
            float4 v1 = __ldg((const float4*)&g_xp[(size_t)s1 * D + lane * 4]);
            a0.x = fmaf(v0.x, e0, a0.x); a0.y = fmaf(v0.y, e0, a0.y);
            a0.z = fmaf(v0.z, e0, a0.z); a0.w = fmaf(v0.w, e0, a0.w);
            a1.x = fmaf(v1.x, e1, a1.x); a1.y = fmaf(v1.y, e1, a1.y);
            a1.z = fmaf(v1.z, e1, a1.z); a1.w = fmaf(v1.w, e1, a1.w);
            d0 += e0; d1 += e1;
        }
        if (j < m) {
            int   s0 = __shfl_sync(0xFFFFFFFFu, sl, j);
            float e0 = __shfl_sync(0xFFFFFFFFu, exl, j);
            float4 v0 = __ldg((const float4*)&g_xp[(size_t)s0 * D + lane * 4]);
            a0.x = fmaf(v0.x, e0, a0.x); a0.y = fmaf(v0.y, e0, a0.y);
            a0.z = fmaf(v0.z, e0, a0.z); a0.w = fmaf(v0.w, e0, a0.w);
            d0 += e0;
        }
    }
    float inv = 1.f / (d0 + d1 + 1e-16f);
    *(float4*)&g_acc[(size_t)wg * D + lane * 4] =
        make_float4((a0.x + a1.x) * inv, (a0.y + a1.y) * inv,
                    (a0.z + a1.z) * inv, (a0.w + a1.w) * inv);
}

// ---------------- GraphNorm stats over out = g_acc + gat_bias ----------------
__global__ __launch_bounds__(128) void k_colstats(const float* __restrict__ gb) {
    int c = threadIdx.x;
    float b = gb[c];
    double s = 0.0, q = 0.0;
    for (int r = blockIdx.x; r < NN; r += gridDim.x) {
        float o = g_acc[(size_t)r * D + c] + b;
        s += o; q += (double)o * o;
    }
    atomicAdd(&g_cs[c], s);
    atomicAdd(&g_cq[c], q);
}

// ---------------- GraphNorm coefficients: norm(o) = o*A + B ----------------
__global__ void k_finalize(const float* __restrict__ gnw, const float* __restrict__ gnb,
                           const float* __restrict__ gms, const float* __restrict__ gatb) {
    int c = threadIdx.x;
    double m  = g_cs[c] / (double)NN;
    double e2 = g_cq[c] / (double)NN;
    double s  = (double)gms[c];
    double var = e2 - 2.0 * s * m * m + s * s * m * m;
    double A = (double)gnw[c] / sqrt(var + 1e-5);
    double B = (double)gnb[c] - s * m * A;
    g_A[c] = (float)A;
    g_B[c] = (float)((double)gatb[c] * A + B);
}

// ---------------- precompute mixed + norm-scaled final weights (full fp32) ----------------
__global__ __launch_bounds__(256) void k_prep(const float* __restrict__ Wc0, const float* __restrict__ bc0,
                                              const float* __restrict__ Wc1, const float* __restrict__ bc1) {
    __shared__ float2 rr[256];
    int j = blockIdx.x, c = threadIdx.x;
    float w0 = Wc0[j * 256 + c], w1 = Wc1[j * 256 + c];
    float wa = ZA * w1 + ZB * w0;
    float wb = ZA * w0 + ZB * w1;
    float pa = 0.f, pb = 0.f;
    if (c < D) {
        float Bv = g_B[c], A = g_A[c];
        pa = wa * Bv; pb = wb * Bv;
        wa *= A; wb *= A;
    }
    g_Wa[j * 256 + c] = wa;
    g_Wb[j * 256 + c] = wb;
    rr[c] = make_float2(pa, pb);
    __syncthreads();
    for (int off = 128; off > 0; off >>= 1) {
        if (c < off) { rr[c].x += rr[c + off].x; rr[c].y += rr[c + off].y; }
        __syncthreads();
    }
    if (c == 0) {
        g_ba[j] = ZA * bc1[j] + ZB * bc0[j] + rr[0].x;
        g_bb[j] = ZA * bc0[j] + ZB * bc1[j] + rr[0].y;
    }
}

// ---------------- final GEMM (tf32x3, inline splits) ----------------
template <int WHICH>
__global__ __launch_bounds__(256) void k_final(const float* __restrict__ x_, float* __restrict__ out) {
    __shared__ __align__(16) float sA[64 * 12];
    __shared__ __align__(16) float sB[128 * 8];
    __shared__ int sIdx[64];
    int cnt = g_cnt[WHICH];
    int base = blockIdx.x * 64;
    if (base >= cnt) return;
    const int*   list = (WHICH == 0) ? g_listT : g_listF;
    const float* W    = (WHICH == 0) ? g_Wa : g_Wb;
    const float* bias = (WHICH == 0) ? g_ba : g_bb;
    int tid = threadIdx.x, lane = tid & 31, warp = tid >> 5;
    int wm = warp >> 2, wn = warp & 3;
    int g = lane >> 2, t = lane & 3;
    if (tid < 64) sIdx[tid] = (base + tid < cnt) ? list[base + tid] : -1;
    __syncthreads();

    float4 acc[2][4];
#pragma unroll
    for (int mt = 0; mt < 2; mt++)
#pragma unroll
        for (int nt = 0; nt < 4; nt++) acc[mt][nt] = make_float4(0.f, 0.f, 0.f, 0.f);

    for (int kc = 0; kc < 32; kc++) {
        if (tid < 128) {
            int row = tid >> 1, seg = tid & 1;
            int aidx = sIdx[row];
            int k0 = kc * 8 + seg * 4;
            float4 av = make_float4(0.f, 0.f, 0.f, 0.f);
            if (aidx >= 0) {
                if (k0 < D) av = *(const float4*)&g_acc[(size_t)aidx * D + k0];
                else        av = *(const float4*)&x_[(size_t)aidx * D + (k0 - D)];
            }
            *(float4*)&sA[row * 12 + seg * 4] = av;
        }
        {
            int j = tid >> 1, seg = tid & 1;
            *(float4*)&sB[j * 8 + seg * 4] = *(const float4*)&W[j * 256 + kc * 8 + seg * 4];
        }
        __syncthreads();
        unsigned ah[2][4], al[2][4];
#pragma unroll
        for (int mt = 0; mt < 2; mt++) {
            int r = wm * 32 + mt * 16 + g;
            sp3(sA[r * 12 + t],           ah[mt][0], al[mt][0]);
            sp3(sA[(r + 8) * 12 + t],     ah[mt][1], al[mt][1]);
            sp3(sA[r * 12 + t + 4],       ah[mt][2], al[mt][2]);
            sp3(sA[(r + 8) * 12 + t + 4], ah[mt][3], al[mt][3]);
        }
#pragma unroll
        for (int nt = 0; nt < 4; nt++) {
            int n = wn * 32 + nt * 8 + g;
            unsigned bh0, bl0, bh1, bl1;
            sp3(sB[n * 8 + t],     bh0, bl0);
            sp3(sB[n * 8 + t + 4], bh1, bl1);
            mma3(acc[0][nt], ah[0], al[0], bh0, bh1, bl0, bl1);
            mma3(acc[1][nt], ah[1], al[1], bh0, bh1, bl0, bl1);
        }
        __syncthreads();
    }
#pragma unroll
    for (int nt = 0; nt < 4; nt++) {
        int cn = wn * 32 + nt * 8 + t * 2;
        float bx = bias[cn], by = bias[cn + 1];
#pragma unroll
        for (int mt = 0; mt < 2; mt++) {
            int r = wm * 32 + mt * 16 + g;
            int i0 = sIdx[r], i1 = sIdx[r + 8];
            float4 u = acc[mt][nt];
            if (i0 >= 0) *(float2*)&out[(size_t)i0 * D + cn] = make_float2(u.x + bx, u.y + by);
            if (i1 >= 0) *(float2*)&out[(size_t)i1 * D + cn] = make_float2(u.z + bx, u.w + by);
        }
    }
}

// ---------------- launch (k_tg deliberately 4th: ncu profiles launch #4) ----------------
extern "C" void kernel_launch(void* const* d_in, const int* in_sizes, int n_in,
                              void* d_out, int out_size) {
    const float* x_      = (const float*)d_in[0];
    const float* W_t0    = (const float*)d_in[2];
    const float* b_t0    = (const float*)d_in[3];
    const float* W_t1    = (const float*)d_in[4];
    const float* b_t1    = (const float*)d_in[5];
    const float* gat_W   = (const float*)d_in[6];
    const float* att_src = (const float*)d_in[7];
    const float* att_dst = (const float*)d_in[8];
    const float* gat_b   = (const float*)d_in[9];
    const float* gn_w    = (const float*)d_in[10];
    const float* gn_b    = (const float*)d_in[11];
    const float* gn_ms   = (const float*)d_in[12];
    const float* W_c0    = (const float*)d_in[13];
    const float* b_c0    = (const float*)d_in[14];
    const float* W_c1    = (const float*)d_in[15];
    const float* b_c1    = (const float*)d_in[16];
    const void*  ei      = d_in[17];
    const void*  mask    = d_in[18];
    float* out = (float*)d_out;

    int gb = (NN + 63) / 64;

    k_detect<<<(NN + 255) / 256, 256>>>(ei, mask);            // 1
    k_convert<<<(TOTE + 255) / 256, 256>>>(ei, mask);         // 2
    k_scan1<<<NBLK, 1024>>>();                                // 3
    k_tg<<<gb, 256>>>(x_, W_t0, b_t0, W_t1, b_t1,             // 4  <- profiled
                      gat_W, att_src, att_dst);
    k_scan2<<<1, 32>>>();                                     // 5
    k_scan3<<<NBLK, 1024>>>();                                // 6
    k_fill<<<(TOTE + 255) / 256, 256>>>();                    // 7
    k_agg<<<(NN * 32 + 255) / 256, 256>>>();                  // 8
    k_colstats<<<512, 128>>>(gat_b);                          // 9
    k_finalize<<<1, 128>>>(gn_w, gn_b, gn_ms, gat_b);         // 10
    k_prep<<<128, 256>>>(W_c0, b_c0, W_c1, b_c1);             // 11
    k_final<0><<<gb, 256>>>(x_, out);                         // 12
    k_final<1><<<gb, 256>>>(x_, out);                         // 13
}

// round 12
// speedup vs baseline: 1.2900x; 1.1047x over previous
#include <cuda_runtime.h>

#define NN 100000
#define EE 1600000
#define TOTE 1700000
#define D 128
#define ZA 0.8f
#define ZB 0.2f
#define NEG 0.2f
#define NBLK 98   // ceil(NN / 1024)

// ---------------- scratch (device globals; no runtime allocation) ----------------
__device__ __align__(256) float  g_xp[NN * D];
__device__ __align__(256) float  g_acc[NN * D];
__device__ __align__(256) float  g_asrc[NN];
__device__ __align__(256) float  g_adst[NN];
__device__ __align__(256) int    g_src[TOTE];
__device__ __align__(256) int    g_dst[TOTE];
__device__ __align__(256) int    g_deg[NN];
__device__ __align__(256) int    g_rowptr[NN + 1];
__device__ __align__(256) int    g_pos[NN];
__device__ __align__(256) int    g_esrc[TOTE];
__device__ __align__(256) float  g_eex[TOTE];
__device__ __align__(256) int    g_bsum[NBLK];
__device__ __align__(256) int    g_boff[NBLK];
__device__ __align__(256) unsigned char g_mask[NN];
__device__ __align__(256) double g_cs[D];
__device__ __align__(256) double g_cq[D];
__device__ __align__(256) float  g_A[D];
__device__ __align__(256) float  g_B[D];
__device__ __align__(256) float  g_Wa[D * 2 * D];
__device__ __align__(256) float  g_Wb[D * 2 * D];
__device__ __align__(256) float  g_ba[D];
__device__ __align__(256) float  g_bb[D];
__device__ __align__(256) int    g_listT[NN];
__device__ __align__(256) int    g_listF[NN];
__device__            int        g_cnt[2];
__device__            int        g_flags[2];

// ---------------- tf32x3 helpers ----------------
__device__ __forceinline__ float tff(float f) {
    unsigned u; asm("cvt.rna.tf32.f32 %0, %1;" : "=r"(u) : "f"(f));
    return __uint_as_float(u);
}
__device__ __forceinline__ void sp3(float f, unsigned& h, unsigned& l) {
    float hf = tff(f);
    h = __float_as_uint(hf);
    l = __float_as_uint(tff(f - hf));
}
__device__ __forceinline__ void mma8(float4& d, const unsigned a[4], unsigned b0, unsigned b1) {
    asm volatile("mma.sync.aligned.m16n8k8.row.col.f32.tf32.tf32.f32 "
                 "{%0,%1,%2,%3},{%4,%5,%6,%7},{%8,%9},{%0,%1,%2,%3};"
                 : "+f"(d.x), "+f"(d.y), "+f"(d.z), "+f"(d.w)
                 : "r"(a[0]), "r"(a[1]), "r"(a[2]), "r"(a[3]), "r"(b0), "r"(b1));
}
// D += A*B with tf32x3 compensation (drops lo*lo term, ~2e-7 rel)
__device__ __forceinline__ void mma3(float4& d, const unsigned ah[4], const unsigned al[4],
                                     unsigned bh0, unsigned bh1, unsigned bl0, unsigned bl1) {
    mma8(d, al, bh0, bh1);
    mma8(d, ah, bl0, bl1);
    mma8(d, ah, bh0, bh1);
}
// ---------------- cp.async helpers ----------------
__device__ __forceinline__ unsigned su(const void* p) {
    return (unsigned)__cvta_generic_to_shared(p);
}
__device__ __forceinline__ void cpa16(unsigned dst, const void* src, bool valid) {
    int sz = valid ? 16 : 0;
    asm volatile("cp.async.cg.shared.global [%0], [%1], 16, %2;"
                 :: "r"(dst), "l"(src), "r"(sz));
}
__device__ __forceinline__ void cpcommit() { asm volatile("cp.async.commit_group;"); }
__device__ __forceinline__ void cpwait0()  { asm volatile("cp.async.wait_group 0;"); }

// ---------------- detect dtypes + zero counters (launch 1) ----------------
__global__ __launch_bounds__(256) void k_detect(const void* ei, const void* mask) {
    int i = blockIdx.x * 256 + threadIdx.x;
    if (i < NN) g_deg[i] = 0;
    if (i < D) { g_cs[i] = 0.0; g_cq[i] = 0.0; }
    if (i == 0) {
        g_cnt[0] = 0; g_cnt[1] = 0;
        const int* e32 = (const int*)ei;
        int allz = 1;
        for (int k = 1; k < 128; k += 2) if (e32[k] != 0) { allz = 0; break; }
        g_flags[0] = allz;
        const unsigned int* m32 = (const unsigned int*)mask;
        int int_like = 1, float_like = 1;
        for (int k = 0; k < 256; k++) {
            unsigned int w = m32[k];
            if (!(w == 0u || w == 1u)) int_like = 0;
            if (!(w == 0u || w == 0x3F800000u)) float_like = 0;
        }
        g_flags[1] = int_like ? 1 : (float_like ? 2 : 0);
    }
}

// ---------------- normalize inputs + degree histogram + mask compaction (launch 2) ----------------
__global__ __launch_bounds__(256) void k_convert(const void* ei, const void* maskp) {
    int i = blockIdx.x * 256 + threadIdx.x;
    int e64 = g_flags[0], mk = g_flags[1];
    if (i < TOTE) {
        int s, d;
        if (i < EE) {
            if (e64) {
                const long long* e = (const long long*)ei;
                s = (int)e[i]; d = (int)e[EE + i];
            } else {
                const int* e = (const int*)ei;
                s = e[i]; d = e[EE + i];
            }
        } else { s = d = i - EE; }
        g_src[i] = s; g_dst[i] = d;
        if ((unsigned)s < NN && (unsigned)d < NN) atomicAdd(&g_deg[d], 1);
    }
    if (i < NN) {
        unsigned char m;
        if (mk == 0)      m = ((const unsigned char*)maskp)[i] != 0;
        else if (mk == 1) m = ((const int*)maskp)[i] != 0;
        else              m = ((const float*)maskp)[i] != 0.f;
        g_mask[i] = m;
        if (m) g_listT[atomicAdd(&g_cnt[0], 1)] = i;
        else   g_listF[atomicAdd(&g_cnt[1], 1)] = i;
    }
}

// ---------------- scan level 1 (launch 3) ----------------
__global__ __launch_bounds__(1024) void k_scan1() {
    __shared__ int sh[1024];
    int b = blockIdx.x, t = threadIdx.x;
    int i = b * 1024 + t;
    sh[t] = (i < NN) ? g_deg[i] : 0;
    __syncthreads();
    for (int off = 512; off > 0; off >>= 1) {
        if (t < off) sh[t] += sh[t + off];
        __syncthreads();
    }
    if (t == 0) g_bsum[b] = sh[0];
}

// ---------------- fused transform+GAT, tf32x3, cp.async double-buffered (launch 4 -> PROFILED) ----
// Aliased smem (42.6 KB):
//  [0,640)      sPS/sPD/sM
//  [640,34432)  sX 64x132 fp32 (live from stage-1 epilogue on)
//    stage-1 aliases (dead once sX is written):
//    sA[2]  : [640,6784)     64x12 fp32 x2
//    sB0[2] : [6784,14976)   128x8 fp32 x2
//    sB1[2] : [14976,23168)  128x8 fp32 x2
//  [34432,42624) sG[2] 128x8 fp32 x2 (stage-2 B tiles)
__global__ __launch_bounds__(256) void k_tg(
    const float* __restrict__ x,
    const float* __restrict__ W0, const float* __restrict__ b0v,
    const float* __restrict__ W1, const float* __restrict__ b1v,
    const float* __restrict__ GW,
    const float* __restrict__ att_s, const float* __restrict__ att_d)
{
    __shared__ __align__(16) char smem_[42624];
    float* sPS = (float*)smem_;
    float* sPD = sPS + 64;
    unsigned char* sM = (unsigned char*)(sPD + 64);
    float* sX  = (float*)(smem_ + 640);
    float* sA  = (float*)(smem_ + 640);    // [2][768]
    float* sB0 = (float*)(smem_ + 6784);   // [2][1024]
    float* sB1 = (float*)(smem_ + 14976);  // [2][1024]
    float* sG  = (float*)(smem_ + 34432);  // [2][1024]

    int tid = threadIdx.x, lane = tid & 31, warp = tid >> 5;
    int wm = warp >> 2, wn = warp & 3;
    int g = lane >> 2, t = lane & 3;
    int base = blockIdx.x * 64;
    int row2 = tid >> 1, seg = tid & 1;    // loader coords

    unsigned uA = su(sA), uB0 = su(sB0), uB1 = su(sB1), uG = su(sG);

    if (tid < 64) {
        sPS[tid] = 0.f; sPD[tid] = 0.f;
        int gr = base + tid;
        sM[tid] = (gr < NN) ? g_mask[gr] : (unsigned char)0;
    }

    float4 acc0[2][4], acc1[2][4];
#pragma unroll
    for (int mt = 0; mt < 2; mt++)
#pragma unroll
        for (int nt = 0; nt < 4; nt++) {
            acc0[mt][nt] = make_float4(0.f, 0.f, 0.f, 0.f);
            acc1[mt][nt] = make_float4(0.f, 0.f, 0.f, 0.f);
        }

    // issue loads for a k-step into buffer buf
    auto issue1 = [&](int kc, int buf) {
        if (tid < 128) {
            int grow = base + row2;
            bool v = grow < NN;
            cpa16(uA + (unsigned)(buf * 768 + row2 * 12 + seg * 4) * 4,
                  &x[(size_t)(v ? grow : 0) * D + kc * 8 + seg * 4], v);
        }
        int go = row2 * D + kc * 8 + seg * 4;
        unsigned so = (unsigned)(buf * 1024 + row2 * 8 + seg * 4) * 4;
        cpa16(uB0 + so, &W0[go], true);
        cpa16(uB1 + so, &W1[go], true);
        cpcommit();
    };

    // ---- stage 1: dual tf32x3 GEMM over K=128, pipelined ----
    issue1(0, 0);
    cpwait0();
    __syncthreads();
    for (int kc = 0; kc < 16; kc++) {
        int cur = kc & 1;
        if (kc < 15) issue1(kc + 1, cur ^ 1);
        const float* cA  = sA  + cur * 768;
        const float* cB0 = sB0 + cur * 1024;
        const float* cB1 = sB1 + cur * 1024;
        unsigned ah[2][4], al[2][4];
#pragma unroll
        for (int mt = 0; mt < 2; mt++) {
            int r = wm * 32 + mt * 16 + g;
            sp3(cA[r * 12 + t],           ah[mt][0], al[mt][0]);
            sp3(cA[(r + 8) * 12 + t],     ah[mt][1], al[mt][1]);
            sp3(cA[r * 12 + t + 4],       ah[mt][2], al[mt][2]);
            sp3(cA[(r + 8) * 12 + t + 4], ah[mt][3], al[mt][3]);
        }
#pragma unroll
        for (int nt = 0; nt < 4; nt++) {
            int n = wn * 32 + nt * 8 + g;
            unsigned bh0, bl0, bh1, bl1;
            sp3(cB0[n * 8 + t],     bh0, bl0);
            sp3(cB0[n * 8 + t + 4], bh1, bl1);
            mma3(acc0[0][nt], ah[0], al[0], bh0, bh1, bl0, bl1);
            mma3(acc0[1][nt], ah[1], al[1], bh0, bh1, bl0, bl1);
            sp3(cB1[n * 8 + t],     bh0, bl0);
            sp3(cB1[n * 8 + t + 4], bh1, bl1);
            mma3(acc1[0][nt], ah[0], al[0], bh0, bh1, bl0, bl1);
            mma3(acc1[1][nt], ah[1], al[1], bh0, bh1, bl0, bl1);
        }
        if (kc < 15) cpwait0();
        __syncthreads();
    }

    // ---- stage-1 epilogue: bias + relu + mix -> sX (overwrites dead A/B buffers) ----
#pragma unroll
    for (int nt = 0; nt < 4; nt++) {
        int cn = wn * 32 + nt * 8 + t * 2;
        float b0x = b0v[cn], b0y = b0v[cn + 1];
        float b1x = b1v[cn], b1y = b1v[cn + 1];
#pragma unroll
        for (int mt = 0; mt < 2; mt++) {
            int r0 = wm * 32 + mt * 16 + g;
            bool m0 = sM[r0] != 0, m1 = sM[r0 + 8] != 0;
            float4 u0 = acc0[mt][nt], u1 = acc1[mt][nt];
            float v0, v1, ra, rb;
            v0 = fmaxf(u0.x + b0x, 0.f); v1 = fmaxf(u1.x + b1x, 0.f);
            ra = m0 ? (ZA * v1 + ZB * v0) : (ZA * v0 + ZB * v1);
            v0 = fmaxf(u0.y + b0y, 0.f); v1 = fmaxf(u1.y + b1y, 0.f);
            rb = m0 ? (ZA * v1 + ZB * v0) : (ZA * v0 + ZB * v1);
            *(float2*)&sX[r0 * 132 + cn] = make_float2(ra, rb);
            v0 = fmaxf(u0.z + b0x, 0.f); v1 = fmaxf(u1.z + b1x, 0.f);
            ra = m1 ? (ZA * v1 + ZB * v0) : (ZA * v0 + ZB * v1);
            v0 = fmaxf(u0.w + b0y, 0.f); v1 = fmaxf(u1.w + b1y, 0.f);
            rb = m1 ? (ZA * v1 + ZB * v0) : (ZA * v0 + ZB * v1);
            *(float2*)&sX[(r0 + 8) * 132 + cn] = make_float2(ra, rb);
        }
    }
    __syncthreads();

    // ---- stage 2: xp = sX @ GW^T (tf32x3), B pipelined ----
#pragma unroll
    for (int mt = 0; mt < 2; mt++)
#pragma unroll
        for (int nt = 0; nt < 4; nt++)
            acc0[mt][nt] = make_float4(0.f, 0.f, 0.f, 0.f);

    auto issue2 = [&](int kc, int buf) {
        cpa16(uG + (unsigned)(buf * 1024 + row2 * 8 + seg * 4) * 4,
              &GW[row2 * D + kc * 8 + seg * 4], true);
        cpcommit();
    };
    issue2(0, 0);
    cpwait0();
    __syncthreads();
    for (int kc = 0; kc < 16; kc++) {
        int cur = kc & 1;
        if (kc < 15) issue2(kc + 1, cur ^ 1);
        const float* cG = sG + cur * 1024;
        unsigned ah[2][4], al[2][4];
#pragma unroll
        for (int mt = 0; mt < 2; mt++) {
            int r = wm * 32 + mt * 16 + g;
            sp3(sX[r * 132 + kc * 8 + t],           ah[mt][0], al[mt][0]);
            sp3(sX[(r + 8) * 132 + kc * 8 + t],     ah[mt][1], al[mt][1]);
            sp3(sX[r * 132 + kc * 8 + t + 4],       ah[mt][2], al[mt][2]);
            sp3(sX[(r + 8) * 132 + kc * 8 + t + 4], ah[mt][3], al[mt][3]);
        }
#pragma unroll
        for (int nt = 0; nt < 4; nt++) {
            int n = wn * 32 + nt * 8 + g;
            unsigned bh0, bl0, bh1, bl1;
            sp3(cG[n * 8 + t],     bh0, bl0);
            sp3(cG[n * 8 + t + 4], bh1, bl1);
            mma3(acc0[0][nt], ah[0], al[0], bh0, bh1, bl0, bl1);
            mma3(acc0[1][nt], ah[1], al[1], bh0, bh1, bl0, bl1);
        }
        if (kc < 15) cpwait0();
        __syncthreads();
    }

    // ---- stage-2 epilogue: write xp, reduce attention dots ----
    float asx[4][2], adx[4][2];
#pragma unroll
    for (int nt = 0; nt < 4; nt++) {
        int cn = wn * 32 + nt * 8 + t * 2;
        asx[nt][0] = att_s[cn]; asx[nt][1] = att_s[cn + 1];
        adx[nt][0] = att_d[cn]; adx[nt][1] = att_d[cn + 1];
    }
#pragma unroll
    for (int mt = 0; mt < 2; mt++) {
        float p0 = 0.f, p1 = 0.f, q0 = 0.f, q1 = 0.f;
#pragma unroll
        for (int nt = 0; nt < 4; nt++) {
            float4 u = acc0[mt][nt];
            p0 += u.x * asx[nt][0] + u.y * asx[nt][1];
            q0 += u.x * adx[nt][0] + u.y * adx[nt][1];
            p1 += u.z * asx[nt][0] + u.w * asx[nt][1];
            q1 += u.z * adx[nt][0] + u.w * adx[nt][1];
        }
        p0 += __shfl_xor_sync(0xFFFFFFFFu, p0, 1); p0 += __shfl_xor_sync(0xFFFFFFFFu, p0, 2);
        q0 += __shfl_xor_sync(0xFFFFFFFFu, q0, 1); q0 += __shfl_xor_sync(0xFFFFFFFFu, q0, 2);
        p1 += __shfl_xor_sync(0xFFFFFFFFu, p1, 1); p1 += __shfl_xor_sync(0xFFFFFFFFu, p1, 2);
        q1 += __shfl_xor_sync(0xFFFFFFFFu, q1, 1); q1 += __shfl_xor_sync(0xFFFFFFFFu, q1, 2);
        if (t == 0) {
            int r0 = wm * 32 + mt * 16 + g;
            atomicAdd(&sPS[r0], p0);     atomicAdd(&sPD[r0], q0);
            atomicAdd(&sPS[r0 + 8], p1); atomicAdd(&sPD[r0 + 8], q1);
        }
    }
#pragma unroll
    for (int mt = 0; mt < 2; mt++)
#pragma unroll
        for (int nt = 0; nt < 4; nt++) {
            int r0 = base + wm * 32 + mt * 16 + g;
            int cn = wn * 32 + nt * 8 + t * 2;
            float4 u = acc0[mt][nt];
            if (r0 < NN)     *(float2*)&g_xp[(size_t)r0 * D + cn]       = make_float2(u.x, u.y);
            if (r0 + 8 < NN) *(float2*)&g_xp[(size_t)(r0 + 8) * D + cn] = make_float2(u.z, u.w);
        }
    __syncthreads();
    if (tid < 64) {
        int gr = base + tid;
        if (gr < NN) { g_asrc[gr] = sPS[tid]; g_adst[gr] = sPD[tid]; }
    }
}

// ---------------- scan levels 2/3 ----------------
__global__ void k_scan2() {
    if (threadIdx.x != 0) return;
    int run = 0;
    for (int b = 0; b < NBLK; b++) { g_boff[b] = run; run += g_bsum[b]; }
    g_rowptr[NN] = run;
}
__global__ __launch_bounds__(1024) void k_scan3() {
    __shared__ int sh[1024];
    int b = blockIdx.x, t = threadIdx.x;
    int i = b * 1024 + t;
    int v = (i < NN) ? g_deg[i] : 0;
    sh[t] = v;
    __syncthreads();
    int acc = v;
    for (int off = 1; off < 1024; off <<= 1) {
        int add = (t >= off) ? sh[t - off] : 0;
        __syncthreads();
        acc += add;
        sh[t] = acc;
        __syncthreads();
    }
    if (i < NN) {
        int ex = acc - v + g_boff[b];
        g_rowptr[i] = ex;
        g_pos[i] = ex;
    }
}

// ---------------- fill dst-sorted edge lists + per-edge exp weights ----------------
__global__ __launch_bounds__(256) void k_fill() {
    int e = blockIdx.x * 256 + threadIdx.x;
    if (e >= TOTE) return;
    int s = g_src[e], d = g_dst[e];
    if ((unsigned)s >= NN || (unsigned)d >= NN) return;
    float al = g_asrc[s] + g_adst[d];
    al = al > 0.f ? al : NEG * al;
    float ex = expf(al);
    int p = atomicAdd(&g_pos[d], 1);
    g_esrc[p] = s;
    g_eex[p] = ex;
}

// ---------------- gather-aggregate: one warp per dst, 2x unrolled ----------------
__global__ __launch_bounds__(256) void k_agg() {
    int wg = (blockIdx.x * 256 + threadIdx.x) >> 5;
    int lane = threadIdx.x & 31;
    if (wg >= NN) return;
    int beg = g_rowptr[wg], end = g_rowptr[wg + 1];
    float4 a0 = make_float4(0.f, 0.f, 0.f, 0.f);
    float4 a1 = make_float4(0.f, 0.f, 0.f, 0.f);
    float d0 = 0.f, d1 = 0.f;
    for (int b = beg; b < end; b += 32) {
        int myi = b + lane;
        int sl = 0; float exl = 0.f;
        if (myi < end) { sl = __ldg(&g_esrc[myi]); exl = __ldg(&g_eex[myi]); }
        int m = min(32, end - b);
        int j = 0;
        for (; j + 2 <= m; j += 2) {
            int   s0 = __shfl_sync(0xFFFFFFFFu, sl, j);
            float e0 = __shfl_sync(0xFFFFFFFFu, exl, j);
            int   s1 = __shfl_sync(0xFFFFFFFFu, sl, j + 1);
            float e1 = __shfl_sync(0xFFFFFFFFu, exl, j + 1);
            float4 v0 = __ldg((const float4*)&g_xp[(size_t)s0 * D + lane * 4]);
            float4 v1 = __ldg((const float4*)&g_xp[(size_t)s1 * D + lane * 4]);
            a0.x = fmaf(v0.x, e0, a0.x); a0.y = fmaf(v0.y, e0, a0.y);
            a0.z = fmaf(v0.z, e0, a0.z); a0.w = fmaf(v0.w, e0, a0.w);
            a1.x = fmaf(v1.x, e1, a1.x); a1.y = fmaf(v1.y, e1, a1.y);
            a1.z = fmaf(v1.z, e1, a1.z); a1.w = fmaf(v1.w, e1, a1.w);
            d0 += e0; d1 += e1;
        }
        if (j < m) {
            int   s0 = __shfl_sync(0xFFFFFFFFu, sl, j);
            float e0 = __shfl_sync(0xFFFFFFFFu, exl, j);
            float4 v0 = __ldg((const float4*)&g_xp[(size_t)s0 * D + lane * 4]);
            a0.x = fmaf(v0.x, e0, a0.x); a0.y = fmaf(v0.y, e0, a0.y);
            a0.z = fmaf(v0.z, e0, a0.z); a0.w = fmaf(v0.w, e0, a0.w);
            d0 += e0;
        }
    }
    float inv = 1.f / (d0 + d1 + 1e-16f);
    *(float4*)&g_acc[(size_t)wg * D + lane * 4] =
        make_float4((a0.x + a1.x) * inv, (a0.y + a1.y) * inv,
                    (a0.z + a1.z) * inv, (a0.w + a1.w) * inv);
}

// ---------------- GraphNorm stats over out = g_acc + gat_bias ----------------
__global__ __launch_bounds__(128) void k_colstats(const float* __restrict__ gb) {
    int c = threadIdx.x;
    float b = gb[c];
    double s = 0.0, q = 0.0;
    for (int r = blockIdx.x; r < NN; r += gridDim.x) {
        float o = g_acc[(size_t)r * D + c] + b;
        s += o; q += (double)o * o;
    }
    atomicAdd(&g_cs[c], s);
    atomicAdd(&g_cq[c], q);
}

// ---------------- GraphNorm coefficients: norm(o) = o*A + B ----------------
__global__ void k_finalize(const float* __restrict__ gnw, const float* __restrict__ gnb,
                           const float* __restrict__ gms, const float* __restrict__ gatb) {
    int c = threadIdx.x;
    double m  = g_cs[c] / (double)NN;
    double e2 = g_cq[c] / (double)NN;
    double s  = (double)gms[c];
    double var = e2 - 2.0 * s * m * m + s * s * m * m;
    double A = (double)gnw[c] / sqrt(var + 1e-5);
    double B = (double)gnb[c] - s * m * A;
    g_A[c] = (float)A;
    g_B[c] = (float)((double)gatb[c] * A + B);
}

// ---------------- precompute mixed + norm-scaled final weights (full fp32) ----------------
__global__ __launch_bounds__(256) void k_prep(const float* __restrict__ Wc0, const float* __restrict__ bc0,
                                              const float* __restrict__ Wc1, const float* __restrict__ bc1) {
    __shared__ float2 rr[256];
    int j = blockIdx.x, c = threadIdx.x;
    float w0 = Wc0[j * 256 + c], w1 = Wc1[j * 256 + c];
    float wa = ZA * w1 + ZB * w0;
    float wb = ZA * w0 + ZB * w1;
    float pa = 0.f, pb = 0.f;
    if (c < D) {
        float Bv = g_B[c], A = g_A[c];
        pa = wa * Bv; pb = wb * Bv;
        wa *= A; wb *= A;
    }
    g_Wa[j * 256 + c] = wa;
    g_Wb[j * 256 + c] = wb;
    rr[c] = make_float2(pa, pb);
    __syncthreads();
    for (int off = 128; off > 0; off >>= 1) {
        if (c < off) { rr[c].x += rr[c + off].x; rr[c].y += rr[c + off].y; }
        __syncthreads();
    }
    if (c == 0) {
        g_ba[j] = ZA * bc1[j] + ZB * bc0[j] + rr[0].x;
        g_bb[j] = ZA * bc0[j] + ZB * bc1[j] + rr[0].y;
    }
}

// ---------------- merged final GEMM (tf32x3, cp.async pipelined, both lists) ----------------
__global__ __launch_bounds__(256) void k_fin(const float* __restrict__ x_, float* __restrict__ out) {
    __shared__ __align__(16) float sA[2 * 64 * 12];
    __shared__ __align__(16) float sB[2 * 128 * 8];
    __shared__ int sIdx[64];
    int c0 = g_cnt[0];
    int nT = (c0 + 63) >> 6;
    int which, base, cnt;
    if ((int)blockIdx.x < nT) { which = 0; base = blockIdx.x * 64; cnt = c0; }
    else { which = 1; base = (blockIdx.x - nT) * 64; cnt = g_cnt[1]; }
    if (base >= cnt) return;
    const int*   list = (which == 0) ? g_listT : g_listF;
    const float* W    = (which == 0) ? g_Wa : g_Wb;
    const float* bias = (which == 0) ? g_ba : g_bb;
    int tid = threadIdx.x, lane = tid & 31, warp = tid >> 5;
    int wm = warp >> 2, wn = warp & 3;
    int g = lane >> 2, t = lane & 3;
    int row2 = tid >> 1, seg = tid & 1;
    unsigned uA = su(sA), uB = su(sB);
    if (tid < 64) sIdx[tid] = (base + tid < cnt) ? list[base + tid] : -1;
    __syncthreads();

    float4 acc[2][4];
#pragma unroll
    for (int mt = 0; mt < 2; mt++)
#pragma unroll
        for (int nt = 0; nt < 4; nt++) acc[mt][nt] = make_float4(0.f, 0.f, 0.f, 0.f);

    auto issue = [&](int kc, int buf) {
        if (tid < 128) {
            int aidx = sIdx[row2];
            int k0 = kc * 8 + seg * 4;
            bool v = aidx >= 0;
            int safe = v ? aidx : 0;
            const float* src = (k0 < D) ? &g_acc[(size_t)safe * D + k0]
                                        : &x_[(size_t)safe * D + (k0 - D)];
            cpa16(uA + (unsigned)(buf * 768 + row2 * 12 + seg * 4) * 4, src, v);
        }
        cpa16(uB + (unsigned)(buf * 1024 + row2 * 8 + seg * 4) * 4,
              &W[row2 * 256 + kc * 8 + seg * 4], true);
        cpcommit();
    };

    issue(0, 0);
    cpwait0();
    __syncthreads();
    for (int kc = 0; kc < 32; kc++) {
        int cur = kc & 1;
        if (kc < 31) issue(kc + 1, cur ^ 1);
        const float* cA = sA + cur * 768;
        const float* cB = sB + cur * 1024;
        unsigned ah[2][4], al[2][4];
#pragma unroll
        for (int mt = 0; mt < 2; mt++) {
            int r = wm * 32 + mt * 16 + g;
            sp3(cA[r * 12 + t],           ah[mt][0], al[mt][0]);
            sp3(cA[(r + 8) * 12 + t],     ah[mt][1], al[mt][1]);
            sp3(cA[r * 12 + t + 4],       ah[mt][2], al[mt][2]);
            sp3(cA[(r + 8) * 12 + t + 4], ah[mt][3], al[mt][3]);
        }
#pragma unroll
        for (int nt = 0; nt < 4; nt++) {
            int n = wn * 32 + nt * 8 + g;
            unsigned bh0, bl0, bh1, bl1;
            sp3(cB[n * 8 + t],     bh0, bl0);
            sp3(cB[n * 8 + t + 4], bh1, bl1);
            mma3(acc[0][nt], ah[0], al[0], bh0, bh1, bl0, bl1);
            mma3(acc[1][nt], ah[1], al[1], bh0, bh1, bl0, bl1);
        }
        if (kc < 31) cpwait0();
        __syncthreads();
    }
#pragma unroll
    for (int nt = 0; nt < 4; nt++) {
        int cn = wn * 32 + nt * 8 + t * 2;
        float bx = bias[cn], by = bias[cn + 1];
#pragma unroll
        for (int mt = 0; mt < 2; mt++) {
            int r = wm * 32 + mt * 16 + g;
            int i0 = sIdx[r], i1 = sIdx[r + 8];
            float4 u = acc[mt][nt];
            if (i0 >= 0) *(float2*)&out[(size_t)i0 * D + cn] = make_float2(u.x + bx, u.y + by);
            if (i1 >= 0) *(float2*)&out[(size_t)i1 * D + cn] = make_float2(u.z + bx, u.w + by);
        }
    }
}

// ---------------- launch (k_tg deliberately 4th: ncu profiles launch #4) ----------------
extern "C" void kernel_launch(void* const* d_in, const int* in_sizes, int n_in,
                              void* d_out, int out_size) {
    const float* x_      = (const float*)d_in[0];
    const float* W_t0    = (const float*)d_in[2];
    const float* b_t0    = (const float*)d_in[3];
    const float* W_t1    = (const float*)d_in[4];
    const float* b_t1    = (const float*)d_in[5];
    const float* gat_W   = (const float*)d_in[6];
    const float* att_src = (const float*)d_in[7];
    const float* att_dst = (const float*)d_in[8];
    const float* gat_b   = (const float*)d_in[9];
    const float* gn_w    = (const float*)d_in[10];
    const float* gn_b    = (const float*)d_in[11];
    const float* gn_ms   = (const float*)d_in[12];
    const float* W_c0    = (const float*)d_in[13];
    const float* b_c0    = (const float*)d_in[14];
    const float* W_c1    = (const float*)d_in[15];
    const float* b_c1    = (const float*)d_in[16];
    const void*  ei      = d_in[17];
    const void*  mask    = d_in[18];
    float* out = (float*)d_out;

    int gb = (NN + 63) / 64;

    k_detect<<<(NN + 255) / 256, 256>>>(ei, mask);            // 1
    k_convert<<<(TOTE + 255) / 256, 256>>>(ei, mask);         // 2
    k_scan1<<<NBLK, 1024>>>();                                // 3
    k_tg<<<gb, 256>>>(x_, W_t0, b_t0, W_t1, b_t1,             // 4  <- profiled
                      gat_W, att_src, att_dst);
    k_scan2<<<1, 32>>>();                                     // 5
    k_scan3<<<NBLK, 1024>>>();                                // 6
    k_fill<<<(TOTE + 255) / 256, 256>>>();                    // 7
    k_agg<<<(NN * 32 + 255) / 256, 256>>>();                  // 8
    k_colstats<<<512, 128>>>(gat_b);                          // 9
    k_finalize<<<1, 128>>>(gn_w, gn_b, gn_ms, gat_b);         // 10
    k_prep<<<128, 256>>>(W_c0, b_c0, W_c1, b_c1);             // 11
    k_fin<<<gb + 1, 256>>>(x_, out);                          // 12 (merged finals)
}

// round 13
// speedup vs baseline: 1.3708x; 1.0627x over previous
#include <cuda_runtime.h>

#define NN 100000
#define EE 1600000
#define TOTE 1700000
#define D 128
#define ZA 0.8f
#define ZB 0.2f
#define NEG 0.2f
#define NBLK 98     // ceil(NN / 1024)
#define NAGG 12500  // NN / 8 (exact)

// ---------------- scratch (device globals; no runtime allocation) ----------------
__device__ __align__(256) float  g_xp[NN * D];
__device__ __align__(256) float  g_acc[NN * D];
__device__ __align__(256) float  g_asrc[NN];
__device__ __align__(256) float  g_adst[NN];
__device__ __align__(256) int    g_src[TOTE];
__device__ __align__(256) int    g_dst[TOTE];
__device__ __align__(256) int    g_deg[NN];
__device__ __align__(256) int    g_rowptr[NN + 1];
__device__ __align__(256) int    g_pos[NN];
__device__ __align__(256) int    g_esrc[TOTE];
__device__ __align__(256) float  g_eex[TOTE];
__device__ __align__(256) int    g_bsum[NBLK];
__device__ __align__(256) int    g_boff[NBLK];
__device__ __align__(256) unsigned char g_mask[NN];
__device__ __align__(256) float  g_psum[NAGG * D];
__device__ __align__(256) float  g_psq [NAGG * D];
__device__ __align__(256) double g_cs[D];
__device__ __align__(256) double g_cq[D];
__device__ __align__(256) float  g_A[D];
__device__ __align__(256) float  g_B[D];
__device__ __align__(256) float  g_Wa[D * 2 * D];
__device__ __align__(256) float  g_Wb[D * 2 * D];
__device__ __align__(256) float  g_ba[D];
__device__ __align__(256) float  g_bb[D];
__device__ __align__(256) int    g_listT[NN];
__device__ __align__(256) int    g_listF[NN];
__device__            int        g_cnt[2];
__device__            int        g_flags[2];

// ---------------- tf32x3 helpers (truncation split: HW reads top 19 bits) ----------------
// hi operand = raw fp32 bits (HW truncates); lo = f - truncate(f) computed via mask.
// lo is EXACTLY the residual of the hi value the MMA consumes; only lo's own
// truncation (~2^-22 rel) and the dropped lo*lo term remain.
__device__ __forceinline__ void sp3t(float f, unsigned& h, unsigned& l) {
    unsigned uf = __float_as_uint(f);
    h = uf;
    l = __float_as_uint(f - __uint_as_float(uf & 0xFFFFE000u));
}
__device__ __forceinline__ void mma8(float4& d, const unsigned a[4], unsigned b0, unsigned b1) {
    asm volatile("mma.sync.aligned.m16n8k8.row.col.f32.tf32.tf32.f32 "
                 "{%0,%1,%2,%3},{%4,%5,%6,%7},{%8,%9},{%0,%1,%2,%3};"
                 : "+f"(d.x), "+f"(d.y), "+f"(d.z), "+f"(d.w)
                 : "r"(a[0]), "r"(a[1]), "r"(a[2]), "r"(a[3]), "r"(b0), "r"(b1));
}
__device__ __forceinline__ void mma3(float4& d, const unsigned ah[4], const unsigned al[4],
                                     unsigned bh0, unsigned bh1, unsigned bl0, unsigned bl1) {
    mma8(d, al, bh0, bh1);
    mma8(d, ah, bl0, bl1);
    mma8(d, ah, bh0, bh1);
}
// ---------------- cp.async helpers ----------------
__device__ __forceinline__ unsigned su(const void* p) {
    return (unsigned)__cvta_generic_to_shared(p);
}
__device__ __forceinline__ void cpa16(unsigned dst, const void* src, bool valid) {
    int sz = valid ? 16 : 0;
    asm volatile("cp.async.cg.shared.global [%0], [%1], 16, %2;"
                 :: "r"(dst), "l"(src), "r"(sz));
}
__device__ __forceinline__ void cpcommit() { asm volatile("cp.async.commit_group;"); }
__device__ __forceinline__ void cpwait0()  { asm volatile("cp.async.wait_group 0;"); }

// ---------------- detect dtypes + zero counters (launch 1) ----------------
__global__ __launch_bounds__(256) void k_detect(const void* ei, const void* mask) {
    int i = blockIdx.x * 256 + threadIdx.x;
    if (i < NN) g_deg[i] = 0;
    if (i < D) { g_cs[i] = 0.0; g_cq[i] = 0.0; }
    if (i == 0) {
        g_cnt[0] = 0; g_cnt[1] = 0;
        const int* e32 = (const int*)ei;
        int allz = 1;
        for (int k = 1; k < 128; k += 2) if (e32[k] != 0) { allz = 0; break; }
        g_flags[0] = allz;
        const unsigned int* m32 = (const unsigned int*)mask;
        int int_like = 1, float_like = 1;
        for (int k = 0; k < 256; k++) {
            unsigned int w = m32[k];
            if (!(w == 0u || w == 1u)) int_like = 0;
            if (!(w == 0u || w == 0x3F800000u)) float_like = 0;
        }
        g_flags[1] = int_like ? 1 : (float_like ? 2 : 0);
    }
}

// ---------------- normalize inputs + degree histogram + mask compaction (launch 2) ----------------
__global__ __launch_bounds__(256) void k_convert(const void* ei, const void* maskp) {
    int i = blockIdx.x * 256 + threadIdx.x;
    int e64 = g_flags[0], mk = g_flags[1];
    if (i < TOTE) {
        int s, d;
        if (i < EE) {
            if (e64) {
                const long long* e = (const long long*)ei;
                s = (int)e[i]; d = (int)e[EE + i];
            } else {
                const int* e = (const int*)ei;
                s = e[i]; d = e[EE + i];
            }
        } else { s = d = i - EE; }
        g_src[i] = s; g_dst[i] = d;
        if ((unsigned)s < NN && (unsigned)d < NN) atomicAdd(&g_deg[d], 1);
    }
    if (i < NN) {
        unsigned char m;
        if (mk == 0)      m = ((const unsigned char*)maskp)[i] != 0;
        else if (mk == 1) m = ((const int*)maskp)[i] != 0;
        else              m = ((const float*)maskp)[i] != 0.f;
        g_mask[i] = m;
        if (m) g_listT[atomicAdd(&g_cnt[0], 1)] = i;
        else   g_listF[atomicAdd(&g_cnt[1], 1)] = i;
    }
}

// ---------------- scan level 1 (launch 3) ----------------
__global__ __launch_bounds__(1024) void k_scan1() {
    __shared__ int sh[1024];
    int b = blockIdx.x, t = threadIdx.x;
    int i = b * 1024 + t;
    sh[t] = (i < NN) ? g_deg[i] : 0;
    __syncthreads();
    for (int off = 512; off > 0; off >>= 1) {
        if (t < off) sh[t] += sh[t + off];
        __syncthreads();
    }
    if (t == 0) g_bsum[b] = sh[0];
}

// ---------------- fused transform+GAT, tf32x3 trunc-split, cp.async (launch 4 -> PROFILED) ----
__global__ __launch_bounds__(256) void k_tg(
    const float* __restrict__ x,
    const float* __restrict__ W0, const float* __restrict__ b0v,
    const float* __restrict__ W1, const float* __restrict__ b1v,
    const float* __restrict__ GW,
    const float* __restrict__ att_s, const float* __restrict__ att_d)
{
    __shared__ __align__(16) char smem_[42624];
    float* sPS = (float*)smem_;
    float* sPD = sPS + 64;
    unsigned char* sM = (unsigned char*)(sPD + 64);
    float* sX  = (float*)(smem_ + 640);
    float* sA  = (float*)(smem_ + 640);    // [2][768]
    float* sB0 = (float*)(smem_ + 6784);   // [2][1024]
    float* sB1 = (float*)(smem_ + 14976);  // [2][1024]
    float* sG  = (float*)(smem_ + 34432);  // [2][1024]

    int tid = threadIdx.x, lane = tid & 31, warp = tid >> 5;
    int wm = warp >> 2, wn = warp & 3;
    int g = lane >> 2, t = lane & 3;
    int base = blockIdx.x * 64;
    int row2 = tid >> 1, seg = tid & 1;

    unsigned uA = su(sA), uB0 = su(sB0), uB1 = su(sB1), uG = su(sG);

    if (tid < 64) {
        sPS[tid] = 0.f; sPD[tid] = 0.f;
        int gr = base + tid;
        sM[tid] = (gr < NN) ? g_mask[gr] : (unsigned char)0;
    }

    float4 acc0[2][4], acc1[2][4];
#pragma unroll
    for (int mt = 0; mt < 2; mt++)
#pragma unroll
        for (int nt = 0; nt < 4; nt++) {
            acc0[mt][nt] = make_float4(0.f, 0.f, 0.f, 0.f);
            acc1[mt][nt] = make_float4(0.f, 0.f, 0.f, 0.f);
        }

    auto issue1 = [&](int kc, int buf) {
        if (tid < 128) {
            int grow = base + row2;
            bool v = grow < NN;
            cpa16(uA + (unsigned)(buf * 768 + row2 * 12 + seg * 4) * 4,
                  &x[(size_t)(v ? grow : 0) * D + kc * 8 + seg * 4], v);
        }
        int go = row2 * D + kc * 8 + seg * 4;
        unsigned so = (unsigned)(buf * 1024 + row2 * 8 + seg * 4) * 4;
        cpa16(uB0 + so, &W0[go], true);
        cpa16(uB1 + so, &W1[go], true);
        cpcommit();
    };

    // ---- stage 1: dual tf32x3 GEMM over K=128, pipelined ----
    issue1(0, 0);
    cpwait0();
    __syncthreads();
    for (int kc = 0; kc < 16; kc++) {
        int cur = kc & 1;
        if (kc < 15) issue1(kc + 1, cur ^ 1);
        const float* cA  = sA  + cur * 768;
        const float* cB0 = sB0 + cur * 1024;
        const float* cB1 = sB1 + cur * 1024;
        unsigned ah[2][4], al[2][4];
#pragma unroll
        for (int mt = 0; mt < 2; mt++) {
            int r = wm * 32 + mt * 16 + g;
            sp3t(cA[r * 12 + t],           ah[mt][0], al[mt][0]);
            sp3t(cA[(r + 8) * 12 + t],     ah[mt][1], al[mt][1]);
            sp3t(cA[r * 12 + t + 4],       ah[mt][2], al[mt][2]);
            sp3t(cA[(r + 8) * 12 + t + 4], ah[mt][3], al[mt][3]);
        }
#pragma unroll
        for (int nt = 0; nt < 4; nt++) {
            int n = wn * 32 + nt * 8 + g;
            unsigned bh0, bl0, bh1, bl1;
            sp3t(cB0[n * 8 + t],     bh0, bl0);
            sp3t(cB0[n * 8 + t + 4], bh1, bl1);
            mma3(acc0[0][nt], ah[0], al[0], bh0, bh1, bl0, bl1);
            mma3(acc0[1][nt], ah[1], al[1], bh0, bh1, bl0, bl1);
            sp3t(cB1[n * 8 + t],     bh0, bl0);
            sp3t(cB1[n * 8 + t + 4], bh1, bl1);
            mma3(acc1[0][nt], ah[0], al[0], bh0, bh1, bl0, bl1);
            mma3(acc1[1][nt], ah[1], al[1], bh0, bh1, bl0, bl1);
        }
        if (kc < 15) cpwait0();
        __syncthreads();
    }

    // ---- stage-1 epilogue: bias + relu + mix -> sX ----
#pragma unroll
    for (int nt = 0; nt < 4; nt++) {
        int cn = wn * 32 + nt * 8 + t * 2;
        float b0x = b0v[cn], b0y = b0v[cn + 1];
        float b1x = b1v[cn], b1y = b1v[cn + 1];
#pragma unroll
        for (int mt = 0; mt < 2; mt++) {
            int r0 = wm * 32 + mt * 16 + g;
            bool m0 = sM[r0] != 0, m1 = sM[r0 + 8] != 0;
            float4 u0 = acc0[mt][nt], u1 = acc1[mt][nt];
            float v0, v1, ra, rb;
            v0 = fmaxf(u0.x + b0x, 0.f); v1 = fmaxf(u1.x + b1x, 0.f);
            ra = m0 ? (ZA * v1 + ZB * v0) : (ZA * v0 + ZB * v1);
            v0 = fmaxf(u0.y + b0y, 0.f); v1 = fmaxf(u1.y + b1y, 0.f);
            rb = m0 ? (ZA * v1 + ZB * v0) : (ZA * v0 + ZB * v1);
            *(float2*)&sX[r0 * 132 + cn] = make_float2(ra, rb);
            v0 = fmaxf(u0.z + b0x, 0.f); v1 = fmaxf(u1.z + b1x, 0.f);
            ra = m1 ? (ZA * v1 + ZB * v0) : (ZA * v0 + ZB * v1);
            v0 = fmaxf(u0.w + b0y, 0.f); v1 = fmaxf(u1.w + b1y, 0.f);
            rb = m1 ? (ZA * v1 + ZB * v0) : (ZA * v0 + ZB * v1);
            *(float2*)&sX[(r0 + 8) * 132 + cn] = make_float2(ra, rb);
        }
    }
    __syncthreads();

    // ---- stage 2: xp = sX @ GW^T ----
#pragma unroll
    for (int mt = 0; mt < 2; mt++)
#pragma unroll
        for (int nt = 0; nt < 4; nt++)
            acc0[mt][nt] = make_float4(0.f, 0.f, 0.f, 0.f);

    auto issue2 = [&](int kc, int buf) {
        cpa16(uG + (unsigned)(buf * 1024 + row2 * 8 + seg * 4) * 4,
              &GW[row2 * D + kc * 8 + seg * 4], true);
        cpcommit();
    };
    issue2(0, 0);
    cpwait0();
    __syncthreads();
    for (int kc = 0; kc < 16; kc++) {
        int cur = kc & 1;
        if (kc < 15) issue2(kc + 1, cur ^ 1);
        const float* cG = sG + cur * 1024;
        unsigned ah[2][4], al[2][4];
#pragma unroll
        for (int mt = 0; mt < 2; mt++) {
            int r = wm * 32 + mt * 16 + g;
            sp3t(sX[r * 132 + kc * 8 + t],           ah[mt][0], al[mt][0]);
            sp3t(sX[(r + 8) * 132 + kc * 8 + t],     ah[mt][1], al[mt][1]);
            sp3t(sX[r * 132 + kc * 8 + t + 4],       ah[mt][2], al[mt][2]);
            sp3t(sX[(r + 8) * 132 + kc * 8 + t + 4], ah[mt][3], al[mt][3]);
        }
#pragma unroll
        for (int nt = 0; nt < 4; nt++) {
            int n = wn * 32 + nt * 8 + g;
            unsigned bh0, bl0, bh1, bl1;
            sp3t(cG[n * 8 + t],     bh0, bl0);
            sp3t(cG[n * 8 + t + 4], bh1, bl1);
            mma3(acc0[0][nt], ah[0], al[0], bh0, bh1, bl0, bl1);
            mma3(acc0[1][nt], ah[1], al[1], bh0, bh1, bl0, bl1);
        }
        if (kc < 15) cpwait0();
        __syncthreads();
    }

    // ---- stage-2 epilogue: write xp, reduce attention dots ----
    float asx[4][2], adx[4][2];
#pragma unroll
    for (int nt = 0; nt < 4; nt++) {
        int cn = wn * 32 + nt * 8 + t * 2;
        asx[nt][0] = att_s[cn]; asx[nt][1] = att_s[cn + 1];
        adx[nt][0] = att_d[cn]; adx[nt][1] = att_d[cn + 1];
    }
#pragma unroll
    for (int mt = 0; mt < 2; mt++) {
        float p0 = 0.f, p1 = 0.f, q0 = 0.f, q1 = 0.f;
#pragma unroll
        for (int nt = 0; nt < 4; nt++) {
            float4 u = acc0[mt][nt];
            p0 += u.x * asx[nt][0] + u.y * asx[nt][1];
            q0 += u.x * adx[nt][0] + u.y * adx[nt][1];
            p1 += u.z * asx[nt][0] + u.w * asx[nt][1];
            q1 += u.z * adx[nt][0] + u.w * adx[nt][1];
        }
        p0 += __shfl_xor_sync(0xFFFFFFFFu, p0, 1); p0 += __shfl_xor_sync(0xFFFFFFFFu, p0, 2);
        q0 += __shfl_xor_sync(0xFFFFFFFFu, q0, 1); q0 += __shfl_xor_sync(0xFFFFFFFFu, q0, 2);
        p1 += __shfl_xor_sync(0xFFFFFFFFu, p1, 1); p1 += __shfl_xor_sync(0xFFFFFFFFu, p1, 2);
        q1 += __shfl_xor_sync(0xFFFFFFFFu, q1, 1); q1 += __shfl_xor_sync(0xFFFFFFFFu, q1, 2);
        if (t == 0) {
            int r0 = wm * 32 + mt * 16 + g;
            atomicAdd(&sPS[r0], p0);     atomicAdd(&sPD[r0], q0);
            atomicAdd(&sPS[r0 + 8], p1); atomicAdd(&sPD[r0 + 8], q1);
        }
    }
#pragma unroll
    for (int mt = 0; mt < 2; mt++)
#pragma unroll
        for (int nt = 0; nt < 4; nt++) {
            int r0 = base + wm * 32 + mt * 16 + g;
            int cn = wn * 32 + nt * 8 + t * 2;
            float4 u = acc0[mt][nt];
            if (r0 < NN)     *(float2*)&g_xp[(size_t)r0 * D + cn]       = make_float2(u.x, u.y);
            if (r0 + 8 < NN) *(float2*)&g_xp[(size_t)(r0 + 8) * D + cn] = make_float2(u.z, u.w);
        }
    __syncthreads();
    if (tid < 64) {
        int gr = base + tid;
        if (gr < NN) { g_asrc[gr] = sPS[tid]; g_adst[gr] = sPD[tid]; }
    }
}

// ---------------- scan levels 2/3 ----------------
__global__ void k_scan2() {
    if (threadIdx.x != 0) return;
    int run = 0;
    for (int b = 0; b < NBLK; b++) { g_boff[b] = run; run += g_bsum[b]; }
    g_rowptr[NN] = run;
}
__global__ __launch_bounds__(1024) void k_scan3() {
    __shared__ int sh[1024];
    int b = blockIdx.x, t = threadIdx.x;
    int i = b * 1024 + t;
    int v = (i < NN) ? g_deg[i] : 0;
    sh[t] = v;
    __syncthreads();
    int acc = v;
    for (int off = 1; off < 1024; off <<= 1) {
        int add = (t >= off) ? sh[t - off] : 0;
        __syncthreads();
        acc += add;
        sh[t] = acc;
        __syncthreads();
    }
    if (i < NN) {
        int ex = acc - v + g_boff[b];
        g_rowptr[i] = ex;
        g_pos[i] = ex;
    }
}

// ---------------- fill dst-sorted edge lists + per-edge exp weights ----------------
__global__ __launch_bounds__(256) void k_fill() {
    int e = blockIdx.x * 256 + threadIdx.x;
    if (e >= TOTE) return;
    int s = g_src[e], d = g_dst[e];
    if ((unsigned)s >= NN || (unsigned)d >= NN) return;
    float al = g_asrc[s] + g_adst[d];
    al = al > 0.f ? al : NEG * al;
    float ex = expf(al);
    int p = atomicAdd(&g_pos[d], 1);
    g_esrc[p] = s;
    g_eex[p] = ex;
}

// ---------------- gather-aggregate + atomics-free fused stats ----------------
// one warp per dst; block = 8 nodes (12500 x 8 = 100000 exactly; all warps valid)
__global__ __launch_bounds__(256) void k_agg() {
    __shared__ float sS[8 * 128], sQ[8 * 128];
    int tid = threadIdx.x, lane = tid & 31, warp = tid >> 5;
    int wg = blockIdx.x * 8 + warp;
    int beg = g_rowptr[wg], end = g_rowptr[wg + 1];
    float4 a0 = make_float4(0.f, 0.f, 0.f, 0.f);
    float4 a1 = make_float4(0.f, 0.f, 0.f, 0.f);
    float d0 = 0.f, d1 = 0.f;
    for (int b = beg; b < end; b += 32) {
        int myi = b + lane;
        int sl = 0; float exl = 0.f;
        if (myi < end) { sl = __ldg(&g_esrc[myi]); exl = __ldg(&g_eex[myi]); }
        int m = min(32, end - b);
        int j = 0;
        for (; j + 2 <= m; j += 2) {
            int   s0 = __shfl_sync(0xFFFFFFFFu, sl, j);
            float e0 = __shfl_sync(0xFFFFFFFFu, exl, j);
            int   s1 = __shfl_sync(0xFFFFFFFFu, sl, j + 1);
            float e1 = __shfl_sync(0xFFFFFFFFu, exl, j + 1);
            float4 v0 = __ldg((const float4*)&g_xp[(size_t)s0 * D + lane * 4]);
            float4 v1 = __ldg((const float4*)&g_xp[(size_t)s1 * D + lane * 4]);
            a0.x = fmaf(v0.x, e0, a0.x); a0.y = fmaf(v0.y, e0, a0.y);
            a0.z = fmaf(v0.z, e0, a0.z); a0.w = fmaf(v0.w, e0, a0.w);
            a1.x = fmaf(v1.x, e1, a1.x); a1.y = fmaf(v1.y, e1, a1.y);
            a1.z = fmaf(v1.z, e1, a1.z); a1.w = fmaf(v1.w, e1, a1.w);
            d0 += e0; d1 += e1;
        }
        if (j < m) {
            int   s0 = __shfl_sync(0xFFFFFFFFu, sl, j);
            float e0 = __shfl_sync(0xFFFFFFFFu, exl, j);
            float4 v0 = __ldg((const float4*)&g_xp[(size_t)s0 * D + lane * 4]);
            a0.x = fmaf(v0.x, e0, a0.x); a0.y = fmaf(v0.y, e0, a0.y);
            a0.z = fmaf(v0.z, e0, a0.z); a0.w = fmaf(v0.w, e0, a0.w);
            d0 += e0;
        }
    }
    float inv = 1.f / (d0 + d1 + 1e-16f);
    float4 o = make_float4((a0.x + a1.x) * inv, (a0.y + a1.y) * inv,
                           (a0.z + a1.z) * inv, (a0.w + a1.w) * inv);
    *(float4*)&g_acc[(size_t)wg * D + lane * 4] = o;
    // per-warp private slot (no atomics, no conflicts)
    int c = lane * 4;
    *(float4*)&sS[warp * 128 + c] = o;
    *(float4*)&sQ[warp * 128 + c] = make_float4(o.x * o.x, o.y * o.y, o.z * o.z, o.w * o.w);
    __syncthreads();
    if (tid < 128) {
        float s = 0.f, q = 0.f;
#pragma unroll
        for (int w = 0; w < 8; w++) { s += sS[w * 128 + tid]; q += sQ[w * 128 + tid]; }
        g_psum[blockIdx.x * 128 + tid] = s;
        g_psq [blockIdx.x * 128 + tid] = q;
    }
}

// ---------------- reduce partials to double sums ----------------
__global__ __launch_bounds__(128) void k_red1() {
    int c = threadIdx.x;
    double s = 0.0, q = 0.0;
    for (int b = blockIdx.x; b < NAGG; b += gridDim.x) {
        s += (double)g_psum[b * 128 + c];
        q += (double)g_psq [b * 128 + c];
    }
    atomicAdd(&g_cs[c], s);
    atomicAdd(&g_cq[c], q);
}

// ---------------- GraphNorm coefficients (stats exclude bias; adjust here) ----------------
__global__ void k_red2(const float* __restrict__ gnw, const float* __restrict__ gnb,
                       const float* __restrict__ gms, const float* __restrict__ gatb) {
    int c = threadIdx.x;
    double S = g_cs[c], Q = g_cq[c];
    double b = (double)gatb[c];
    double m  = (S + (double)NN * b) / (double)NN;                 // E[acc + bias]
    double e2 = (Q + 2.0 * b * S + (double)NN * b * b) / (double)NN;
    double s  = (double)gms[c];
    double var = e2 - 2.0 * s * m * m + s * s * m * m;
    double A = (double)gnw[c] / sqrt(var + 1e-5);
    double B = (double)gnb[c] - s * m * A;
    g_A[c] = (float)A;
    g_B[c] = (float)(b * A + B);
}

// ---------------- precompute mixed + norm-scaled final weights ----------------
__global__ __launch_bounds__(256) void k_prep(const float* __restrict__ Wc0, const float* __restrict__ bc0,
                                              const float* __restrict__ Wc1, const float* __restrict__ bc1) {
    __shared__ float2 rr[256];
    int j = blockIdx.x, c = threadIdx.x;
    float w0 = Wc0[j * 256 + c], w1 = Wc1[j * 256 + c];
    float wa = ZA * w1 + ZB * w0;
    float wb = ZA * w0 + ZB * w1;
    float pa = 0.f, pb = 0.f;
    if (c < D) {
        float Bv = g_B[c], A = g_A[c];
        pa = wa * Bv; pb = wb * Bv;
        wa *= A; wb *= A;
    }
    g_Wa[j * 256 + c] = wa;
    g_Wb[j * 256 + c] = wb;
    rr[c] = make_float2(pa, pb);
    __syncthreads();
    for (int off = 128; off > 0; off >>= 1) {
        if (c < off) { rr[c].x += rr[c + off].x; rr[c].y += rr[c + off].y; }
        __syncthreads();
    }
    if (c == 0) {
        g_ba[j] = ZA * bc1[j] + ZB * bc0[j] + rr[0].x;
        g_bb[j] = ZA * bc0[j] + ZB * bc1[j] + rr[0].y;
    }
}

// ---------------- merged final GEMM (tf32x3 trunc-split, cp.async, both lists) ----------------
__global__ __launch_bounds__(256) void k_fin(const float* __restrict__ x_, float* __restrict__ out) {
    __shared__ __align__(16) float sA[2 * 64 * 12];
    __shared__ __align__(16) float sB[2 * 128 * 8];
    __shared__ int sIdx[64];
    int c0 = g_cnt[0];
    int nT = (c0 + 63) >> 6;
    int which, base, cnt;
    if ((int)blockIdx.x < nT) { which = 0; base = blockIdx.x * 64; cnt = c0; }
    else { which = 1; base = (blockIdx.x - nT) * 64; cnt = g_cnt[1]; }
    if (base >= cnt) return;
    const int*   list = (which == 0) ? g_listT : g_listF;
    const float* W    = (which == 0) ? g_Wa : g_Wb;
    const float* bias = (which == 0) ? g_ba : g_bb;
    int tid = threadIdx.x, lane = tid & 31, warp = tid >> 5;
    int wm = warp >> 2, wn = warp & 3;
    int g = lane >> 2, t = lane & 3;
    int row2 = tid >> 1, seg = tid & 1;
    unsigned uA = su(sA), uB = su(sB);
    if (tid < 64) sIdx[tid] = (base + tid < cnt) ? list[base + tid] : -1;
    __syncthreads();

    float4 acc[2][4];
#pragma unroll
    for (int mt = 0; mt < 2; mt++)
#pragma unroll
        for (int nt = 0; nt < 4; nt++) acc[mt][nt] = make_float4(0.f, 0.f, 0.f, 0.f);

    auto issue = [&](int kc, int buf) {
        if (tid < 128) {
            int aidx = sIdx[row2];
            int k0 = kc * 8 + seg * 4;
            bool v = aidx >= 0;
            int safe = v ? aidx : 0;
            const float* src = (k0 < D) ? &g_acc[(size_t)safe * D + k0]
                                        : &x_[(size_t)safe * D + (k0 - D)];
            cpa16(uA + (unsigned)(buf * 768 + row2 * 12 + seg * 4) * 4, src, v);
        }
        cpa16(uB + (unsigned)(buf * 1024 + row2 * 8 + seg * 4) * 4,
              &W[row2 * 256 + kc * 8 + seg * 4], true);
        cpcommit();
    };

    issue(0, 0);
    cpwait0();
    __syncthreads();
    for (int kc = 0; kc < 32; kc++) {
        int cur = kc & 1;
        if (kc < 31) issue(kc + 1, cur ^ 1);
        const float* cA = sA + cur * 768;
        const float* cB = sB + cur * 1024;
        unsigned ah[2][4], al[2][4];
#pragma unroll
        for (int mt = 0; mt < 2; mt++) {
            int r = wm * 32 + mt * 16 + g;
            sp3t(cA[r * 12 + t],           ah[mt][0], al[mt][0]);
            sp3t(cA[(r + 8) * 12 + t],     ah[mt][1], al[mt][1]);
            sp3t(cA[r * 12 + t + 4],       ah[mt][2], al[mt][2]);
            sp3t(cA[(r + 8) * 12 + t + 4], ah[mt][3], al[mt][3]);
        }
#pragma unroll
        for (int nt = 0; nt < 4; nt++) {
            int n = wn * 32 + nt * 8 + g;
            unsigned bh0, bl0, bh1, bl1;
            sp3t(cB[n * 8 + t],     bh0, bl0);
            sp3t(cB[n * 8 + t + 4], bh1, bl1);
            mma3(acc[0][nt], ah[0], al[0], bh0, bh1, bl0, bl1);
            mma3(acc[1][nt], ah[1], al[1], bh0, bh1, bl0, bl1);
        }
        if (kc < 31) cpwait0();
        __syncthreads();
    }
#pragma unroll
    for (int nt = 0; nt < 4; nt++) {
        int cn = wn * 32 + nt * 8 + t * 2;
        float bx = bias[cn], by = bias[cn + 1];
#pragma unroll
        for (int mt = 0; mt < 2; mt++) {
            int r = wm * 32 + mt * 16 + g;
            int i0 = sIdx[r], i1 = sIdx[r + 8];
            float4 u = acc[mt][nt];
            if (i0 >= 0) *(float2*)&out[(size_t)i0 * D + cn] = make_float2(u.x + bx, u.y + by);
            if (i1 >= 0) *(float2*)&out[(size_t)i1 * D + cn] = make_float2(u.z + bx, u.w + by);
        }
    }
}

// ---------------- launch (k_tg deliberately 4th: ncu profiles launch #4) ----------------
extern "C" void kernel_launch(void* const* d_in, const int* in_sizes, int n_in,
                              void* d_out, int out_size) {
    const float* x_      = (const float*)d_in[0];
    const float* W_t0    = (const float*)d_in[2];
    const float* b_t0    = (const float*)d_in[3];
    const float* W_t1    = (const float*)d_in[4];
    const float* b_t1    = (const float*)d_in[5];
    const float* gat_W   = (const float*)d_in[6];
    const float* att_src = (const float*)d_in[7];
    const float* att_dst = (const float*)d_in[8];
    const float* gat_b   = (const float*)d_in[9];
    const float* gn_w    = (const float*)d_in[10];
    const float* gn_b    = (const float*)d_in[11];
    const float* gn_ms   = (const float*)d_in[12];
    const float* W_c0    = (const float*)d_in[13];
    const float* b_c0    = (const float*)d_in[14];
    const float* W_c1    = (const float*)d_in[15];
    const float* b_c1    = (const float*)d_in[16];
    const void*  ei      = d_in[17];
    const void*  mask    = d_in[18];
    float* out = (float*)d_out;

    int gb = (NN + 63) / 64;

    k_detect<<<(NN + 255) / 256, 256>>>(ei, mask);            // 1
    k_convert<<<(TOTE + 255) / 256, 256>>>(ei, mask);         // 2
    k_scan1<<<NBLK, 1024>>>();                                // 3
    k_tg<<<gb, 256>>>(x_, W_t0, b_t0, W_t1, b_t1,             // 4  <- profiled
                      gat_W, att_src, att_dst);
    k_scan2<<<1, 32>>>();                                     // 5
    k_scan3<<<NBLK, 1024>>>();                                // 6
    k_fill<<<(TOTE + 255) / 256, 256>>>();                    // 7
    k_agg<<<NAGG, 256>>>();                                   // 8
    k_red1<<<64, 128>>>();                                    // 9
    k_red2<<<1, 128>>>(gn_w, gn_b, gn_ms, gat_b);             // 10
    k_prep<<<128, 256>>>(W_c0, b_c0, W_c1, b_c1);             // 11
    k_fin<<<gb + 1, 256>>>(x_, out);                          // 12
}